// round 9
// baseline (speedup 1.0000x reference)
#include <cuda_runtime.h>
#include <cuda_bf16.h>
#include <stdint.h>
#include <math.h>

typedef unsigned int u32;

#define NN 20000
#define EE 320000
#define DD 128
#define HH 3
#define HD (HH*DD)      /* 384 */
#define LL 3
#define GG 64
#define TWO_D (2*DD)    /* 256 */
#define NEG_SLOPE 0.2f

// ---------------- scratch (device globals; no allocation allowed) ----------------
__device__ float g_h[(size_t)NN*HD];
__device__ float g_featA[(size_t)NN*DD];
__device__ float g_featB[(size_t)NN*DD];
__device__ float g_gate[NN];
__device__ float g_sns[NN*HH];
__device__ float g_snd[NN*HH];
__device__ int   g_deg[NN];
__device__ int   g_rowptr[NN+1];
__device__ int   g_cursor[NN];
__device__ int   g_csrsrc[EE];
__device__ int   g_gstart[GG];
__device__ int   g_gend[GG];

// bf16 split buffers
__device__ __nv_bfloat16 g_fhiA[(size_t)NN*DD];
__device__ __nv_bfloat16 g_floA[(size_t)NN*DD];
__device__ __nv_bfloat16 g_fhiB[(size_t)NN*DD];
__device__ __nv_bfloat16 g_floB[(size_t)NN*DD];
__device__ __nv_bfloat16 g_agghi[(size_t)NN*HD];
__device__ __nv_bfloat16 g_agglo[(size_t)NN*HD];
__device__ __nv_bfloat16 g_wfchi[(size_t)LL*HD*DD];
__device__ __nv_bfloat16 g_wfclo[(size_t)LL*HD*DD];
__device__ __nv_bfloat16 g_wtrhi[(size_t)LL*DD*HD];
__device__ __nv_bfloat16 g_wtrlo[(size_t)LL*DD*HD];
__device__ __nv_bfloat16 g_wp1hi[(size_t)LL*TWO_D*DD];
__device__ __nv_bfloat16 g_wp1lo[(size_t)LL*TWO_D*DD];

__device__ __forceinline__ void split_bf16(float v, __nv_bfloat16& hi, __nv_bfloat16& lo) {
    hi = __float2bfloat16_rn(v);
    lo = __float2bfloat16_rn(v - __bfloat162float(hi));
}

// ---------------- setup kernels ----------------
__global__ void copy_split_kernel(const float* __restrict__ srcp, float* __restrict__ out) {
    int i = blockIdx.x*blockDim.x + threadIdx.x;
    if (i < NN*DD) {
        float v = srcp[i];
        g_featA[i] = v;
        __nv_bfloat16 hi, lo; split_bf16(v, hi, lo);
        g_fhiA[i] = hi; g_floA[i] = lo;
    }
    if (i < NN*HH) { g_sns[i] = 0.f; g_snd[i] = 0.f; }
    if (i < NN)    { g_gate[i] = 0.f; g_deg[i] = 0; }
    if (i < GG*DD) out[i] = 0.f;
}

__global__ void conv_all_kernel(const float* __restrict__ fc, const float* __restrict__ tr,
                                const float* __restrict__ p1) {
    const int NFC = LL*HD*DD;
    const int NTR = LL*DD*HD;
    const int NP1 = LL*TWO_D*DD;
    int i = blockIdx.x*blockDim.x + threadIdx.x;
    if (i < NFC) {
        __nv_bfloat16 h, l; split_bf16(fc[i], h, l);
        g_wfchi[i] = h; g_wfclo[i] = l;
    } else if (i < NFC + NTR) {
        int j = i - NFC;
        __nv_bfloat16 h, l; split_bf16(tr[j], h, l);
        g_wtrhi[j] = h; g_wtrlo[j] = l;
    } else if (i < NFC + NTR + NP1) {
        int j = i - NFC - NTR;
        __nv_bfloat16 h, l; split_bf16(p1[j], h, l);
        g_wp1hi[j] = h; g_wp1lo[j] = l;
    }
    if (i < GG) { g_gstart[i] = NN; g_gend[i] = 0; }
}

__global__ void zero_layer_kernel() {
    int i = blockIdx.x*blockDim.x + threadIdx.x;
    if (i < NN*HH) { g_sns[i] = 0.f; g_snd[i] = 0.f; }
    if (i < NN)    g_gate[i] = 0.f;
}

__global__ void hist_kernel(const int* __restrict__ dst) {
    int e = blockIdx.x*blockDim.x + threadIdx.x;
    if (e < EE) atomicAdd(&g_deg[dst[e]], 1);
}

__global__ void scan_kernel() {
    __shared__ int part[1024];
    int t = threadIdx.x;
    const int CH = 20;
    int base = t * CH;
    int local[CH];
    int s = 0;
#pragma unroll
    for (int i = 0; i < CH; i++) {
        int idx = base + i;
        int v = (idx < NN) ? g_deg[idx] : 0;
        local[i] = s;
        s += v;
    }
    part[t] = s;
    __syncthreads();
    for (int off = 1; off < 1024; off <<= 1) {
        int v = (t >= off) ? part[t - off] : 0;
        __syncthreads();
        part[t] += v;
        __syncthreads();
    }
    int offset = (t > 0) ? part[t - 1] : 0;
#pragma unroll
    for (int i = 0; i < CH; i++) {
        int idx = base + i;
        if (idx < NN) {
            int r = offset + local[i];
            g_rowptr[idx] = r;
            g_cursor[idx] = r;
        }
    }
    if (t == 0) g_rowptr[NN] = part[1023];
}

__global__ void scatter_kernel(const int* __restrict__ src, const int* __restrict__ dst) {
    int e = blockIdx.x*blockDim.x + threadIdx.x;
    if (e < EE) {
        int p = atomicAdd(&g_cursor[dst[e]], 1);
        g_csrsrc[p] = src[e];
    }
}

__global__ void gbounds_kernel(const int* __restrict__ gid) {
    int i = blockIdx.x*blockDim.x + threadIdx.x;
    if (i < NN) {
        int g = gid[i];
        atomicMin(&g_gstart[g], i);
        atomicMax(&g_gend[g], i + 1);
    }
}

// ---------------- tensor-core GEMM (3-stage cp.async, 1 sync/chunk) ----------------
// C[M, cols] = A[M,K] @ B[rows,K]^T, bf16 split: Ahi*Bhi + Ahi*Blo + Alo*Bhi
// Block tile 128x64, K-chunk 32, 256 threads (8 warps 4x2).

__device__ __forceinline__ void ldm_x4(u32 addr, u32& r0, u32& r1, u32& r2, u32& r3) {
    asm volatile("ldmatrix.sync.aligned.m8n8.x4.shared.b16 {%0,%1,%2,%3}, [%4];"
        : "=r"(r0), "=r"(r1), "=r"(r2), "=r"(r3) : "r"(addr));
}

__device__ __forceinline__ void mma16816(float* c, const u32* a, const u32* b) {
    asm volatile(
        "mma.sync.aligned.m16n8k16.row.col.f32.bf16.bf16.f32 "
        "{%0,%1,%2,%3}, {%4,%5,%6,%7}, {%8,%9}, {%0,%1,%2,%3};"
        : "+f"(c[0]), "+f"(c[1]), "+f"(c[2]), "+f"(c[3])
        : "r"(a[0]), "r"(a[1]), "r"(a[2]), "r"(a[3]), "r"(b[0]), "r"(b[1]));
}

#define CP16(dst, src, sz) asm volatile( \
    "cp.async.cg.shared.global [%0], [%1], 16, %2;" :: "r"(dst), "l"(src), "r"(sz))
#define CP_COMMIT() asm volatile("cp.async.commit_group;")
#define CP_WAIT1()  asm volatile("cp.async.wait_group 1;")
#define CP_WAIT0()  asm volatile("cp.async.wait_group 0;")

#define A_PAD 40   /* row stride in bf16 elems: 80B -> conflict-free ldmatrix */
#define SA_MAT (128*A_PAD)
#define SB_MAT (64*A_PAD)
#define NSTAGE 3

// issue one K-chunk's copies into stage st (6 x 16B per thread)
#define GISSUE(kc, st) { \
    int kb = ((kc) << 5) + aq; \
    u32 sa = sA_u + (u32)((st)*2*SA_MAT)*2u; \
    u32 sb2 = sB_u + (u32)((st)*2*SB_MAT)*2u; \
    CP16(sa + aoffA0,              Ahi + (size_t)arow0c * K + kb, szA0); \
    CP16(sa + aoffA1,              Ahi + (size_t)arow1c * K + kb, szA1); \
    CP16(sa + (u32)SA_MAT*2u + aoffA0, Alo + (size_t)arow0c * K + kb, szA0); \
    CP16(sa + (u32)SA_MAT*2u + aoffA1, Alo + (size_t)arow1c * K + kb, szA1); \
    CP16(sb2 + boffB,              Bhi + (size_t)(n0 + br0) * K + kb, 16); \
    CP16(sb2 + (u32)SB_MAT*2u + boffB, Blo + (size_t)(n0 + br0) * K + kb, 16); \
}

__global__ void __launch_bounds__(256, 2) gemm_bf16split(
    int M, int Nd, int K, int col_base,
    const __nv_bfloat16* __restrict__ Ahi, const __nv_bfloat16* __restrict__ Alo,
    const __nv_bfloat16* __restrict__ Bhi, const __nv_bfloat16* __restrict__ Blo,
    const float* __restrict__ bias, const float* __restrict__ resid,
    float* __restrict__ C, __nv_bfloat16* __restrict__ Chi, __nv_bfloat16* __restrict__ Clo,
    int do_relu,
    float* __restrict__ gatep, const float* __restrict__ p2w,
    float* __restrict__ snsp, float* __restrict__ sndp,
    const float* __restrict__ ansp, const float* __restrict__ andp)
{
    extern __shared__ __nv_bfloat16 smem[];
    __nv_bfloat16* sA = smem;                        // [NSTAGE][2 hl][128*A_PAD]
    __nv_bfloat16* sB = smem + NSTAGE*2*SA_MAT;      // [NSTAGE][2 hl][64*A_PAD]

    const int tid  = threadIdx.x;
    const int lane = tid & 31;
    const int w    = tid >> 5;
    const int wm   = w & 3;
    const int wn   = w >> 2;
    const int m0   = blockIdx.x * 128;
    const int n0   = blockIdx.y * 64;
    const int nk   = K >> 5;

    float acc[2][4][4];
#pragma unroll
    for (int a = 0; a < 2; a++)
#pragma unroll
        for (int b = 0; b < 4; b++)
#pragma unroll
            for (int c = 0; c < 4; c++) acc[a][b][c] = 0.f;

    const u32 sA_u = (u32)__cvta_generic_to_shared(sA);
    const u32 sB_u = (u32)__cvta_generic_to_shared(sB);

    // ldmatrix lane addressing
    const int a_row_in = (lane & 7) + ((lane >> 3) & 1) * 8;
    const int a_kofs   = (lane >> 4) * 8;
    const int b_sub    = lane >> 3;
    const int b_row_in = (lane & 7) + (b_sub >> 1) * 8;
    const int b_kofs   = (b_sub & 1) * 8;

    // per-thread copy mapping (4 threads per row, 16B each)
    const int ar0 = tid >> 2;
    const int aq  = (tid & 3) * 8;
    const int br0 = tid >> 2;
    const int arow0 = m0 + ar0;
    const int arow1 = m0 + ar0 + 64;
    const int arow0c = (arow0 < M) ? arow0 : (M - 1);
    const int arow1c = (arow1 < M) ? arow1 : (M - 1);
    const u32 szA0 = (arow0 < M) ? 16u : 0u;
    const u32 szA1 = (arow1 < M) ? 16u : 0u;
    const u32 aoffA0 = (u32)(ar0 * A_PAD + aq) * 2u;
    const u32 aoffA1 = (u32)((ar0 + 64) * A_PAD + aq) * 2u;
    const u32 boffB  = (u32)(br0 * A_PAD + aq) * 2u;

    // prologue: 2-deep lookahead
    GISSUE(0, 0);
    CP_COMMIT();
    if (nk > 1) { GISSUE(1, 1); CP_COMMIT(); }

    int cur = 0;
    for (int kc = 0; kc < nk; kc++) {
        if (kc + 1 < nk) { CP_WAIT1(); } else { CP_WAIT0(); }
        __syncthreads();   // stage kc visible; all warps done with stage kc-1

#pragma unroll
        for (int ks = 0; ks < 2; ks++) {
            u32 Af[2][2][4];
            u32 Bf[2][4][2];
#pragma unroll
            for (int hl = 0; hl < 2; hl++) {
                const u32 abase = sA_u +
                    (u32)(((cur * 2 + hl) * 128 + wm * 32) * A_PAD) * 2u;
#pragma unroll
                for (int mt = 0; mt < 2; mt++) {
                    u32 addr = abase +
                        (u32)((mt * 16 + a_row_in) * A_PAD + ks * 16 + a_kofs) * 2u;
                    ldm_x4(addr, Af[hl][mt][0], Af[hl][mt][1], Af[hl][mt][2], Af[hl][mt][3]);
                }
                const u32 bbase = sB_u +
                    (u32)(((cur * 2 + hl) * 64 + wn * 32) * A_PAD) * 2u;
#pragma unroll
                for (int pr = 0; pr < 2; pr++) {
                    u32 addr2 = bbase +
                        (u32)((pr * 16 + b_row_in) * A_PAD + ks * 16 + b_kofs) * 2u;
                    u32 q0, q1, q2, q3;
                    ldm_x4(addr2, q0, q1, q2, q3);
                    Bf[hl][pr * 2 + 0][0] = q0; Bf[hl][pr * 2 + 0][1] = q1;
                    Bf[hl][pr * 2 + 1][0] = q2; Bf[hl][pr * 2 + 1][1] = q3;
                }
            }
#pragma unroll
            for (int mt = 0; mt < 2; mt++)
#pragma unroll
                for (int nt = 0; nt < 4; nt++) {
                    mma16816(acc[mt][nt], Af[0][mt], Bf[0][nt]);  // hi*hi
                    mma16816(acc[mt][nt], Af[0][mt], Bf[1][nt]);  // hi*lo
                    mma16816(acc[mt][nt], Af[1][mt], Bf[0][nt]);  // lo*hi
                }
        }

        // issue stage kc+2 into slot (kc+2)%3 == (kc-1)%3 (safe: sync above)
        if (kc + 2 < nk) {
            int st = kc + 2 - ((kc + 2) / NSTAGE) * NSTAGE;
            GISSUE(kc + 2, st);
            CP_COMMIT();
        }
        cur++; if (cur == NSTAGE) cur = 0;
    }

    // epilogue
    const int gr = lane >> 2;
    const int gc = (lane & 3) * 2;
    const int head = (col_base + n0 + wn * 32) >> 7;
#pragma unroll
    for (int mt = 0; mt < 2; mt++) {
#pragma unroll
        for (int half = 0; half < 2; half++) {
            int m = m0 + wm * 32 + mt * 16 + gr + half * 8;
            if (m >= M) continue;
            float gpart = 0.f, ps = 0.f, pt = 0.f;
#pragma unroll
            for (int nt = 0; nt < 4; nt++) {
                int gn = col_base + n0 + wn * 32 + nt * 8 + gc;
                float v0 = acc[mt][nt][half * 2 + 0];
                float v1 = acc[mt][nt][half * 2 + 1];
                if (bias) { v0 += bias[gn]; v1 += bias[gn + 1]; }
                if (do_relu) { v0 = fmaxf(v0, 0.f); v1 = fmaxf(v1, 0.f); }
                if (resid) {
                    v0 += resid[(size_t)m * Nd + gn];
                    v1 += resid[(size_t)m * Nd + gn + 1];
                }
                if (gatep) {
                    gpart += v0 * __ldg(p2w + gn) + v1 * __ldg(p2w + gn + 1);
                }
                if (snsp) {
                    ps += v0 * __ldg(ansp + gn) + v1 * __ldg(ansp + gn + 1);
                    pt += v0 * __ldg(andp + gn) + v1 * __ldg(andp + gn + 1);
                }
                if (C) {
                    float2 vv; vv.x = v0; vv.y = v1;
                    *(float2*)(C + (size_t)m * Nd + gn) = vv;
                }
                if (Chi) {
                    __nv_bfloat16 h0, l0, h1, l1;
                    split_bf16(v0, h0, l0);
                    split_bf16(v1, h1, l1);
                    __nv_bfloat162 hh; hh.x = h0; hh.y = h1;
                    __nv_bfloat162 ll; ll.x = l0; ll.y = l1;
                    *(__nv_bfloat162*)(Chi + (size_t)m * Nd + gn) = hh;
                    *(__nv_bfloat162*)(Clo + (size_t)m * Nd + gn) = ll;
                }
            }
            if (gatep) atomicAdd(gatep + m, gpart);
            if (snsp) {
                atomicAdd(snsp + m * 3 + head, ps);
                atomicAdd(sndp + m * 3 + head, pt);
            }
        }
    }
}

// ---------------- edge softmax + aggregation: one warp per dst node ----------------
__device__ __forceinline__ float leaky(float x) { return x > 0.f ? x : NEG_SLOPE * x; }

__global__ void gat_edge_kernel() {
    int v = (blockIdx.x * blockDim.x + threadIdx.x) >> 5;
    int lane = threadIdx.x & 31;
    if (v >= NN) return;
    int beg = g_rowptr[v], end = g_rowptr[v + 1];
    float snd0 = g_snd[v * 3 + 0], snd1 = g_snd[v * 3 + 1], snd2 = g_snd[v * 3 + 2];

    float m0 = -1e30f, m1 = -1e30f, m2 = -1e30f;
    for (int e = beg + lane; e < end; e += 32) {
        int s = g_csrsrc[e];
        m0 = fmaxf(m0, leaky(g_sns[s * 3 + 0] + snd0));
        m1 = fmaxf(m1, leaky(g_sns[s * 3 + 1] + snd1));
        m2 = fmaxf(m2, leaky(g_sns[s * 3 + 2] + snd2));
    }
#pragma unroll
    for (int o = 16; o; o >>= 1) {
        m0 = fmaxf(m0, __shfl_xor_sync(0xffffffffu, m0, o));
        m1 = fmaxf(m1, __shfl_xor_sync(0xffffffffu, m1, o));
        m2 = fmaxf(m2, __shfl_xor_sync(0xffffffffu, m2, o));
    }

    float acc[12];
#pragma unroll
    for (int j = 0; j < 12; j++) acc[j] = 0.f;
    float ws0 = 0.f, ws1 = 0.f, ws2 = 0.f;

    for (int e = beg; e < end; e++) {
        int s = g_csrsrc[e];
        float w0 = __expf(leaky(g_sns[s * 3 + 0] + snd0) - m0);
        float w1 = __expf(leaky(g_sns[s * 3 + 1] + snd1) - m1);
        float w2 = __expf(leaky(g_sns[s * 3 + 2] + snd2) - m2);
        ws0 += w0; ws1 += w1; ws2 += w2;
        const float* hr = g_h + (size_t)s * HD;
#pragma unroll
        for (int j = 0; j < 12; j++) {
            float wv = (j < 4) ? w0 : (j < 8) ? w1 : w2;
            acc[j] += wv * hr[j * 32 + lane];
        }
    }

    float r0 = ws0 > 0.f ? 1.f / ws0 : 0.f;
    float r1 = ws1 > 0.f ? 1.f / ws1 : 0.f;
    float r2 = ws2 > 0.f ? 1.f / ws2 : 0.f;
    __nv_bfloat16* ah = g_agghi + (size_t)v * HD;
    __nv_bfloat16* al = g_agglo + (size_t)v * HD;
#pragma unroll
    for (int j = 0; j < 12; j++) {
        float rv = (j < 4) ? r0 : (j < 8) ? r1 : r2;
        float val = acc[j] * rv;
        __nv_bfloat16 h, l; split_bf16(val, h, l);
        ah[j * 32 + lane] = h;
        al[j * 32 + lane] = l;
    }
}

// ---------------- global attention pooling ----------------
__global__ void pool_kernel(const float* __restrict__ feat, float* __restrict__ out, float scale) {
    int g = blockIdx.x;
    int d = threadIdx.x;
    int s = g_gstart[g], e = g_gend[g];
    __shared__ float red[128];

    float m = -1e30f;
    for (int i = s + d; i < e; i += 128) m = fmaxf(m, g_gate[i]);
    red[d] = m; __syncthreads();
    for (int o = 64; o; o >>= 1) { if (d < o) red[d] = fmaxf(red[d], red[d + o]); __syncthreads(); }
    m = red[0]; __syncthreads();

    float sum = 0.f;
    for (int i = s + d; i < e; i += 128) sum += __expf(g_gate[i] - m);
    red[d] = sum; __syncthreads();
    for (int o = 64; o; o >>= 1) { if (d < o) red[d] += red[d + o]; __syncthreads(); }
    sum = red[0]; __syncthreads();

    float accv = 0.f;
    for (int i = s; i < e; i++) {
        float wv = __expf(g_gate[i] - m);
        accv += wv * feat[(size_t)i * DD + d];
    }
    if (e > s && sum > 0.f) out[g * DD + d] += scale * accv / sum;
}

// ---------------- launch ----------------
extern "C" void kernel_launch(void* const* d_in, const int* in_sizes, int n_in,
                              void* d_out, int out_size)
{
    const float* feat    = (const float*)d_in[0];
    const int*   src     = (const int*)d_in[1];
    const int*   dst     = (const int*)d_in[2];
    const int*   gid     = (const int*)d_in[3];
    const float* fc_w    = (const float*)d_in[4];
    const float* a_ns    = (const float*)d_in[5];
    const float* a_nd    = (const float*)d_in[6];
    const float* trans_w = (const float*)d_in[7];
    const float* trans_b = (const float*)d_in[8];
    const float* p1_w    = (const float*)d_in[9];
    const float* p1_b    = (const float*)d_in[10];
    const float* p2_w    = (const float*)d_in[11];
    const float* p2_b    = (const float*)d_in[12];
    (void)p2_b;  // per-graph softmax over gate is shift-invariant
    float* out = (float*)d_out;

    float *p_h, *p_featA, *p_featB, *p_gate, *p_sns, *p_snd;
    cudaGetSymbolAddress((void**)&p_h, g_h);
    cudaGetSymbolAddress((void**)&p_featA, g_featA);
    cudaGetSymbolAddress((void**)&p_featB, g_featB);
    cudaGetSymbolAddress((void**)&p_gate, g_gate);
    cudaGetSymbolAddress((void**)&p_sns, g_sns);
    cudaGetSymbolAddress((void**)&p_snd, g_snd);

    __nv_bfloat16 *p_fhiA, *p_floA, *p_fhiB, *p_floB, *p_agghi, *p_agglo;
    __nv_bfloat16 *p_wfchi, *p_wfclo, *p_wtrhi, *p_wtrlo, *p_wp1hi, *p_wp1lo;
    cudaGetSymbolAddress((void**)&p_fhiA, g_fhiA);
    cudaGetSymbolAddress((void**)&p_floA, g_floA);
    cudaGetSymbolAddress((void**)&p_fhiB, g_fhiB);
    cudaGetSymbolAddress((void**)&p_floB, g_floB);
    cudaGetSymbolAddress((void**)&p_agghi, g_agghi);
    cudaGetSymbolAddress((void**)&p_agglo, g_agglo);
    cudaGetSymbolAddress((void**)&p_wfchi, g_wfchi);
    cudaGetSymbolAddress((void**)&p_wfclo, g_wfclo);
    cudaGetSymbolAddress((void**)&p_wtrhi, g_wtrhi);
    cudaGetSymbolAddress((void**)&p_wtrlo, g_wtrlo);
    cudaGetSymbolAddress((void**)&p_wp1hi, g_wp1hi);
    cudaGetSymbolAddress((void**)&p_wp1lo, g_wp1lo);

    const int SMEM_GEMM = (NSTAGE*2*SA_MAT + NSTAGE*2*SB_MAT) * (int)sizeof(__nv_bfloat16);
    cudaFuncSetAttribute(gemm_bf16split, cudaFuncAttributeMaxDynamicSharedMemorySize, SMEM_GEMM);

    const int gx = (NN + 127) / 128;
    const int warpBlocks = (NN + 7) / 8;
    const int NCONV = LL*(HD*DD + DD*HD + TWO_D*DD);

    // launch 0: copy+split input, zero everything (incl. g_deg)
    copy_split_kernel<<<(NN * DD + 255) / 256, 256>>>(feat, out);
    // launch 1: all weight converts (+ gb_init)
    conv_all_kernel<<<(NCONV + 255) / 256, 256>>>(fc_w, trans_w, p1_w);

    // launches 2,3,4: layer-0 h-GEMM in 3 column slices (+ fused attn scores)
    for (int sl = 0; sl < 3; sl++) {
        gemm_bf16split<<<dim3(gx, 2), 256, SMEM_GEMM>>>(NN, HD, DD, sl * 128,
            p_fhiA, p_floA,
            p_wfchi + (size_t)sl * 128 * DD, p_wfclo + (size_t)sl * 128 * DD,
            (const float*)0, (const float*)0, p_h,
            (__nv_bfloat16*)0, (__nv_bfloat16*)0, 0,
            (float*)0, (const float*)0,
            p_sns, p_snd, a_ns, a_nd);
    }

    // CSR build (by dst)
    hist_kernel<<<(EE + 255) / 256, 256>>>(dst);
    scan_kernel<<<1, 1024>>>();
    scatter_kernel<<<(EE + 255) / 256, 256>>>(src, dst);
    gbounds_kernel<<<(NN + 255) / 256, 256>>>(gid);

    for (int d = 0; d < LL; d++) {
        int pp = d & 1;
        float* fin  = pp ? p_featB : p_featA;
        float* fout = pp ? p_featA : p_featB;
        __nv_bfloat16* finhi = pp ? p_fhiB : p_fhiA;
        __nv_bfloat16* finlo = pp ? p_floB : p_floA;
        __nv_bfloat16* fouthi = pp ? p_fhiA : p_fhiB;
        __nv_bfloat16* foutlo = pp ? p_floA : p_floB;

        if (d > 0) {
            zero_layer_kernel<<<(NN*HH + 255) / 256, 256>>>();
            gemm_bf16split<<<dim3(gx, HD / 64), 256, SMEM_GEMM>>>(NN, HD, DD, 0,
                finhi, finlo, p_wfchi + (size_t)d * HD * DD, p_wfclo + (size_t)d * HD * DD,
                (const float*)0, (const float*)0, p_h,
                (__nv_bfloat16*)0, (__nv_bfloat16*)0, 0,
                (float*)0, (const float*)0,
                p_sns, p_snd, a_ns + (size_t)d * HD, a_nd + (size_t)d * HD);
        }

        gat_edge_kernel<<<warpBlocks, 256>>>();

        // fout = relu?(agg @ trans_w[d]^T + b) + fin   [N, 128] (+ bf16 split out)
        gemm_bf16split<<<dim3(gx, DD / 64), 256, SMEM_GEMM>>>(NN, DD, HD, 0,
            p_agghi, p_agglo, p_wtrhi + (size_t)d * DD * HD, p_wtrlo + (size_t)d * DD * HD,
            trans_b + (size_t)d * DD, fin, fout, fouthi, foutlo, (d < LL - 1) ? 1 : 0,
            (float*)0, (const float*)0, (float*)0, (float*)0, (const float*)0, (const float*)0);

        // gate[m] = sum_n relu(fout @ p1_w[d]^T + p1_b)[m,n] * p2_w[n]
        gemm_bf16split<<<dim3(gx, TWO_D / 64), 256, SMEM_GEMM>>>(NN, TWO_D, DD, 0,
            fouthi, foutlo, p_wp1hi + (size_t)d * TWO_D * DD, p_wp1lo + (size_t)d * TWO_D * DD,
            p1_b + (size_t)d * TWO_D, (const float*)0, (float*)0,
            (__nv_bfloat16*)0, (__nv_bfloat16*)0, 1,
            p_gate, p2_w + (size_t)d * TWO_D,
            (float*)0, (float*)0, (const float*)0, (const float*)0);

        pool_kernel<<<GG, 128>>>(fout, out, 1.0f / LL);
    }
}

// round 10
// speedup vs baseline: 1.0935x; 1.0935x over previous
#include <cuda_runtime.h>
#include <cuda_bf16.h>
#include <stdint.h>
#include <math.h>

typedef unsigned int u32;

#define NN 20000
#define EE 320000
#define DD 128
#define HH 3
#define HD (HH*DD)      /* 384 */
#define LL 3
#define GG 64
#define TWO_D (2*DD)    /* 256 */
#define NEG_SLOPE 0.2f

// ---------------- scratch (device globals; no allocation allowed) ----------------
__device__ float g_h[(size_t)NN*HD];
__device__ float g_featA[(size_t)NN*DD];
__device__ float g_featB[(size_t)NN*DD];
__device__ float g_gate[NN];
__device__ float g_sns[NN*HH];
__device__ float g_snd[NN*HH];
__device__ int   g_deg[NN];
__device__ int   g_rowptr[NN+1];
__device__ int   g_cursor[NN];
__device__ int   g_csrsrc[EE];
__device__ int   g_gstart[GG];
__device__ int   g_gend[GG];

// bf16 split buffers
__device__ __nv_bfloat16 g_fhiA[(size_t)NN*DD];
__device__ __nv_bfloat16 g_floA[(size_t)NN*DD];
__device__ __nv_bfloat16 g_fhiB[(size_t)NN*DD];
__device__ __nv_bfloat16 g_floB[(size_t)NN*DD];
__device__ __nv_bfloat16 g_agghi[(size_t)NN*HD];
__device__ __nv_bfloat16 g_agglo[(size_t)NN*HD];
__device__ __nv_bfloat16 g_wfchi[(size_t)LL*HD*DD];
__device__ __nv_bfloat16 g_wfclo[(size_t)LL*HD*DD];
__device__ __nv_bfloat16 g_wtrhi[(size_t)LL*DD*HD];
__device__ __nv_bfloat16 g_wtrlo[(size_t)LL*DD*HD];
__device__ __nv_bfloat16 g_wp1hi[(size_t)LL*TWO_D*DD];
__device__ __nv_bfloat16 g_wp1lo[(size_t)LL*TWO_D*DD];

__device__ __forceinline__ void split_bf16(float v, __nv_bfloat16& hi, __nv_bfloat16& lo) {
    hi = __float2bfloat16_rn(v);
    lo = __float2bfloat16_rn(v - __bfloat162float(hi));
}

// ---------------- setup kernels ----------------
__global__ void copy_split_kernel(const float* __restrict__ srcp, float* __restrict__ out) {
    int i = blockIdx.x*blockDim.x + threadIdx.x;
    if (i < NN*DD) {
        float v = srcp[i];
        g_featA[i] = v;
        __nv_bfloat16 hi, lo; split_bf16(v, hi, lo);
        g_fhiA[i] = hi; g_floA[i] = lo;
    }
    if (i < NN*HH) { g_sns[i] = 0.f; g_snd[i] = 0.f; }
    if (i < NN)    { g_gate[i] = 0.f; g_deg[i] = 0; }
    if (i < GG*DD) out[i] = 0.f;
}

__global__ void conv_all_kernel(const float* __restrict__ fc, const float* __restrict__ tr,
                                const float* __restrict__ p1) {
    const int NFC = LL*HD*DD;
    const int NTR = LL*DD*HD;
    const int NP1 = LL*TWO_D*DD;
    int i = blockIdx.x*blockDim.x + threadIdx.x;
    if (i < NFC) {
        __nv_bfloat16 h, l; split_bf16(fc[i], h, l);
        g_wfchi[i] = h; g_wfclo[i] = l;
    } else if (i < NFC + NTR) {
        int j = i - NFC;
        __nv_bfloat16 h, l; split_bf16(tr[j], h, l);
        g_wtrhi[j] = h; g_wtrlo[j] = l;
    } else if (i < NFC + NTR + NP1) {
        int j = i - NFC - NTR;
        __nv_bfloat16 h, l; split_bf16(p1[j], h, l);
        g_wp1hi[j] = h; g_wp1lo[j] = l;
    }
    if (i < GG) { g_gstart[i] = NN; g_gend[i] = 0; }
}

__global__ void zero_layer_kernel() {
    int i = blockIdx.x*blockDim.x + threadIdx.x;
    if (i < NN*HH) { g_sns[i] = 0.f; g_snd[i] = 0.f; }
    if (i < NN)    g_gate[i] = 0.f;
}

__global__ void hist_kernel(const int* __restrict__ dst) {
    int e = blockIdx.x*blockDim.x + threadIdx.x;
    if (e < EE) atomicAdd(&g_deg[dst[e]], 1);
}

__global__ void scan_kernel() {
    __shared__ int part[1024];
    int t = threadIdx.x;
    const int CH = 20;
    int base = t * CH;
    int local[CH];
    int s = 0;
#pragma unroll
    for (int i = 0; i < CH; i++) {
        int idx = base + i;
        int v = (idx < NN) ? g_deg[idx] : 0;
        local[i] = s;
        s += v;
    }
    part[t] = s;
    __syncthreads();
    for (int off = 1; off < 1024; off <<= 1) {
        int v = (t >= off) ? part[t - off] : 0;
        __syncthreads();
        part[t] += v;
        __syncthreads();
    }
    int offset = (t > 0) ? part[t - 1] : 0;
#pragma unroll
    for (int i = 0; i < CH; i++) {
        int idx = base + i;
        if (idx < NN) {
            int r = offset + local[i];
            g_rowptr[idx] = r;
            g_cursor[idx] = r;
        }
    }
    if (t == 0) g_rowptr[NN] = part[1023];
}

__global__ void scatter_kernel(const int* __restrict__ src, const int* __restrict__ dst) {
    int e = blockIdx.x*blockDim.x + threadIdx.x;
    if (e < EE) {
        int p = atomicAdd(&g_cursor[dst[e]], 1);
        g_csrsrc[p] = src[e];
    }
}

__global__ void gbounds_kernel(const int* __restrict__ gid) {
    int i = blockIdx.x*blockDim.x + threadIdx.x;
    if (i < NN) {
        int g = gid[i];
        atomicMin(&g_gstart[g], i);
        atomicMax(&g_gend[g], i + 1);
    }
}

// ---------------- tensor-core GEMM (3-stage cp.async, swizzled smem, 1 sync/chunk) ----
// C[M, cols] = A[M,K] @ B[rows,K]^T, bf16 split: Ahi*Bhi + Ahi*Blo + Alo*Bhi
// Block tile 128x64, K-chunk 32, 256 threads (8 warps 4x2), 3 CTAs/SM.
// smem rows are 64B (32 bf16), XOR-swizzled: addr = row*64 + ((c ^ ((row>>1)&3))<<4)

__device__ __forceinline__ void ldm_x4(u32 addr, u32& r0, u32& r1, u32& r2, u32& r3) {
    asm volatile("ldmatrix.sync.aligned.m8n8.x4.shared.b16 {%0,%1,%2,%3}, [%4];"
        : "=r"(r0), "=r"(r1), "=r"(r2), "=r"(r3) : "r"(addr));
}

__device__ __forceinline__ void mma16816(float* c, const u32* a, const u32* b) {
    asm volatile(
        "mma.sync.aligned.m16n8k16.row.col.f32.bf16.bf16.f32 "
        "{%0,%1,%2,%3}, {%4,%5,%6,%7}, {%8,%9}, {%0,%1,%2,%3};"
        : "+f"(c[0]), "+f"(c[1]), "+f"(c[2]), "+f"(c[3])
        : "r"(a[0]), "r"(a[1]), "r"(a[2]), "r"(a[3]), "r"(b[0]), "r"(b[1]));
}

#define CP16(dst, src, sz) asm volatile( \
    "cp.async.cg.shared.global [%0], [%1], 16, %2;" :: "r"(dst), "l"(src), "r"(sz))
#define CP_COMMIT() asm volatile("cp.async.commit_group;")
#define CP_WAIT1()  asm volatile("cp.async.wait_group 1;")
#define CP_WAIT0()  asm volatile("cp.async.wait_group 0;")

#define A_BYTES (128*64)              /* 8192: 128 rows x 64B */
#define B_BYTES (64*64)               /* 4096 */
#define STAGE_BYTES (2*A_BYTES + 2*B_BYTES)   /* 24576 */
#define NSTAGE 3
#define SWZ(row, c) (((u32)(row) << 6) + (u32)(((c) ^ (((row) >> 1) & 3)) << 4))

// issue one K-chunk's copies into stage st (6 x 16B per thread)
#define GISSUE(kc, st) { \
    int kb = ((kc) << 5) + cq * 8; \
    u32 sbase = smem_u + (u32)((st) * STAGE_BYTES); \
    CP16(sbase + aoff0,                       Ahi + (size_t)arow0c * K + kb, szA0); \
    CP16(sbase + aoff0 + 4096u,               Ahi + (size_t)arow1c * K + kb, szA1); \
    CP16(sbase + (u32)A_BYTES + aoff0,        Alo + (size_t)arow0c * K + kb, szA0); \
    CP16(sbase + (u32)A_BYTES + aoff0 + 4096u, Alo + (size_t)arow1c * K + kb, szA1); \
    CP16(sbase + (u32)(2*A_BYTES) + boff,     Bhi + (size_t)(n0 + br0) * K + kb, 16); \
    CP16(sbase + (u32)(2*A_BYTES + B_BYTES) + boff, Blo + (size_t)(n0 + br0) * K + kb, 16); \
}

__global__ void __launch_bounds__(256, 3) gemm_bf16split(
    int M, int Nd, int K, int col_base,
    const __nv_bfloat16* __restrict__ Ahi, const __nv_bfloat16* __restrict__ Alo,
    const __nv_bfloat16* __restrict__ Bhi, const __nv_bfloat16* __restrict__ Blo,
    const float* __restrict__ bias, const float* __restrict__ resid,
    float* __restrict__ C, __nv_bfloat16* __restrict__ Chi, __nv_bfloat16* __restrict__ Clo,
    int do_relu,
    float* __restrict__ gatep, const float* __restrict__ p2w,
    float* __restrict__ snsp, float* __restrict__ sndp,
    const float* __restrict__ ansp, const float* __restrict__ andp)
{
    extern __shared__ __nv_bfloat16 smem[];

    const int tid  = threadIdx.x;
    const int lane = tid & 31;
    const int w    = tid >> 5;
    const int wm   = w & 3;
    const int wn   = w >> 2;
    const int m0   = blockIdx.x * 128;
    const int n0   = blockIdx.y * 64;
    const int nk   = K >> 5;

    float acc[2][4][4];
#pragma unroll
    for (int a = 0; a < 2; a++)
#pragma unroll
        for (int b = 0; b < 4; b++)
#pragma unroll
            for (int c = 0; c < 4; c++) acc[a][b][c] = 0.f;

    const u32 smem_u = (u32)__cvta_generic_to_shared(smem);

    // ldmatrix lane addressing
    const int a_row_in = (lane & 7) + ((lane >> 3) & 1) * 8;
    const int a_chalf  = lane >> 4;          // 16B column half within ks
    const int b_sub    = lane >> 3;
    const int b_row_in = (lane & 7) + (b_sub >> 1) * 8;
    const int b_chalf  = b_sub & 1;

    // per-thread copy mapping (4 threads per row, 16B each)
    const int ar0 = tid >> 2;
    const int cq  = tid & 3;                 // 16B column 0..3
    const int br0 = ar0;
    const int arow0 = m0 + ar0;
    const int arow1 = m0 + ar0 + 64;
    const int arow0c = (arow0 < M) ? arow0 : (M - 1);
    const int arow1c = (arow1 < M) ? arow1 : (M - 1);
    const u32 szA0 = (arow0 < M) ? 16u : 0u;
    const u32 szA1 = (arow1 < M) ? 16u : 0u;
    const u32 aoff0 = SWZ(ar0, cq);          // row+64 has same swizzle bits: +4096
    const u32 boff  = SWZ(br0, cq);

    // prologue: 2-deep lookahead
    GISSUE(0, 0);
    CP_COMMIT();
    if (nk > 1) { GISSUE(1, 1); CP_COMMIT(); }

    int cur = 0;
    for (int kc = 0; kc < nk; kc++) {
        if (kc + 1 < nk) { CP_WAIT1(); } else { CP_WAIT0(); }
        __syncthreads();   // stage kc visible; all warps done with stage kc-1

        const u32 stbase = smem_u + (u32)(cur * STAGE_BYTES);
#pragma unroll
        for (int ks = 0; ks < 2; ks++) {
            u32 Af[2][2][4];
            u32 Bf[2][4][2];
#pragma unroll
            for (int hl = 0; hl < 2; hl++) {
                const u32 abase = stbase + (u32)(hl * A_BYTES);
#pragma unroll
                for (int mt = 0; mt < 2; mt++) {
                    int row = wm * 32 + mt * 16 + a_row_in;
                    u32 addr = abase + SWZ(row, ks * 2 + a_chalf);
                    ldm_x4(addr, Af[hl][mt][0], Af[hl][mt][1], Af[hl][mt][2], Af[hl][mt][3]);
                }
                const u32 bbase = stbase + (u32)(2 * A_BYTES + hl * B_BYTES);
#pragma unroll
                for (int pr = 0; pr < 2; pr++) {
                    int row = wn * 32 + pr * 16 + b_row_in;
                    u32 addr2 = bbase + SWZ(row, ks * 2 + b_chalf);
                    u32 q0, q1, q2, q3;
                    ldm_x4(addr2, q0, q1, q2, q3);
                    Bf[hl][pr * 2 + 0][0] = q0; Bf[hl][pr * 2 + 0][1] = q1;
                    Bf[hl][pr * 2 + 1][0] = q2; Bf[hl][pr * 2 + 1][1] = q3;
                }
            }
#pragma unroll
            for (int mt = 0; mt < 2; mt++)
#pragma unroll
                for (int nt = 0; nt < 4; nt++) {
                    mma16816(acc[mt][nt], Af[0][mt], Bf[0][nt]);  // hi*hi
                    mma16816(acc[mt][nt], Af[0][mt], Bf[1][nt]);  // hi*lo
                    mma16816(acc[mt][nt], Af[1][mt], Bf[0][nt]);  // lo*hi
                }
        }

        // issue stage kc+2 into slot (kc+2)%3 == (kc-1)%3 (safe: sync above)
        if (kc + 2 < nk) {
            int st = kc + 2 - ((kc + 2) / NSTAGE) * NSTAGE;
            GISSUE(kc + 2, st);
            CP_COMMIT();
        }
        cur++; if (cur == NSTAGE) cur = 0;
    }

    // epilogue
    const int gr = lane >> 2;
    const int gc = (lane & 3) * 2;
    const int head = (col_base + n0 + wn * 32) >> 7;
#pragma unroll
    for (int mt = 0; mt < 2; mt++) {
#pragma unroll
        for (int half = 0; half < 2; half++) {
            int m = m0 + wm * 32 + mt * 16 + gr + half * 8;
            if (m >= M) continue;
            float gpart = 0.f, ps = 0.f, pt = 0.f;
#pragma unroll
            for (int nt = 0; nt < 4; nt++) {
                int gn = col_base + n0 + wn * 32 + nt * 8 + gc;
                float v0 = acc[mt][nt][half * 2 + 0];
                float v1 = acc[mt][nt][half * 2 + 1];
                if (bias) { v0 += bias[gn]; v1 += bias[gn + 1]; }
                if (do_relu) { v0 = fmaxf(v0, 0.f); v1 = fmaxf(v1, 0.f); }
                if (resid) {
                    v0 += resid[(size_t)m * Nd + gn];
                    v1 += resid[(size_t)m * Nd + gn + 1];
                }
                if (gatep) {
                    gpart += v0 * __ldg(p2w + gn) + v1 * __ldg(p2w + gn + 1);
                }
                if (snsp) {
                    ps += v0 * __ldg(ansp + gn) + v1 * __ldg(ansp + gn + 1);
                    pt += v0 * __ldg(andp + gn) + v1 * __ldg(andp + gn + 1);
                }
                if (C) {
                    float2 vv; vv.x = v0; vv.y = v1;
                    *(float2*)(C + (size_t)m * Nd + gn) = vv;
                }
                if (Chi) {
                    __nv_bfloat16 h0, l0, h1, l1;
                    split_bf16(v0, h0, l0);
                    split_bf16(v1, h1, l1);
                    __nv_bfloat162 hh; hh.x = h0; hh.y = h1;
                    __nv_bfloat162 ll; ll.x = l0; ll.y = l1;
                    *(__nv_bfloat162*)(Chi + (size_t)m * Nd + gn) = hh;
                    *(__nv_bfloat162*)(Clo + (size_t)m * Nd + gn) = ll;
                }
            }
            if (gatep) atomicAdd(gatep + m, gpart);
            if (snsp) {
                atomicAdd(snsp + m * 3 + head, ps);
                atomicAdd(sndp + m * 3 + head, pt);
            }
        }
    }
}

// ---------------- edge softmax + aggregation: one warp per dst node ----------------
__device__ __forceinline__ float leaky(float x) { return x > 0.f ? x : NEG_SLOPE * x; }

__global__ void gat_edge_kernel() {
    int v = (blockIdx.x * blockDim.x + threadIdx.x) >> 5;
    int lane = threadIdx.x & 31;
    if (v >= NN) return;
    int beg = g_rowptr[v], end = g_rowptr[v + 1];
    float snd0 = g_snd[v * 3 + 0], snd1 = g_snd[v * 3 + 1], snd2 = g_snd[v * 3 + 2];

    float m0 = -1e30f, m1 = -1e30f, m2 = -1e30f;
    for (int e = beg + lane; e < end; e += 32) {
        int s = g_csrsrc[e];
        m0 = fmaxf(m0, leaky(g_sns[s * 3 + 0] + snd0));
        m1 = fmaxf(m1, leaky(g_sns[s * 3 + 1] + snd1));
        m2 = fmaxf(m2, leaky(g_sns[s * 3 + 2] + snd2));
    }
#pragma unroll
    for (int o = 16; o; o >>= 1) {
        m0 = fmaxf(m0, __shfl_xor_sync(0xffffffffu, m0, o));
        m1 = fmaxf(m1, __shfl_xor_sync(0xffffffffu, m1, o));
        m2 = fmaxf(m2, __shfl_xor_sync(0xffffffffu, m2, o));
    }

    float acc[12];
#pragma unroll
    for (int j = 0; j < 12; j++) acc[j] = 0.f;
    float ws0 = 0.f, ws1 = 0.f, ws2 = 0.f;

    for (int e = beg; e < end; e++) {
        int s = g_csrsrc[e];
        float w0 = __expf(leaky(g_sns[s * 3 + 0] + snd0) - m0);
        float w1 = __expf(leaky(g_sns[s * 3 + 1] + snd1) - m1);
        float w2 = __expf(leaky(g_sns[s * 3 + 2] + snd2) - m2);
        ws0 += w0; ws1 += w1; ws2 += w2;
        const float* hr = g_h + (size_t)s * HD;
#pragma unroll
        for (int j = 0; j < 12; j++) {
            float wv = (j < 4) ? w0 : (j < 8) ? w1 : w2;
            acc[j] += wv * hr[j * 32 + lane];
        }
    }

    float r0 = ws0 > 0.f ? 1.f / ws0 : 0.f;
    float r1 = ws1 > 0.f ? 1.f / ws1 : 0.f;
    float r2 = ws2 > 0.f ? 1.f / ws2 : 0.f;
    __nv_bfloat16* ah = g_agghi + (size_t)v * HD;
    __nv_bfloat16* al = g_agglo + (size_t)v * HD;
#pragma unroll
    for (int j = 0; j < 12; j++) {
        float rv = (j < 4) ? r0 : (j < 8) ? r1 : r2;
        float val = acc[j] * rv;
        __nv_bfloat16 h, l; split_bf16(val, h, l);
        ah[j * 32 + lane] = h;
        al[j * 32 + lane] = l;
    }
}

// ---------------- global attention pooling ----------------
__global__ void pool_kernel(const float* __restrict__ feat, float* __restrict__ out, float scale) {
    int g = blockIdx.x;
    int d = threadIdx.x;
    int s = g_gstart[g], e = g_gend[g];
    __shared__ float red[128];

    float m = -1e30f;
    for (int i = s + d; i < e; i += 128) m = fmaxf(m, g_gate[i]);
    red[d] = m; __syncthreads();
    for (int o = 64; o; o >>= 1) { if (d < o) red[d] = fmaxf(red[d], red[d + o]); __syncthreads(); }
    m = red[0]; __syncthreads();

    float sum = 0.f;
    for (int i = s + d; i < e; i += 128) sum += __expf(g_gate[i] - m);
    red[d] = sum; __syncthreads();
    for (int o = 64; o; o >>= 1) { if (d < o) red[d] += red[d + o]; __syncthreads(); }
    sum = red[0]; __syncthreads();

    float accv = 0.f;
    for (int i = s; i < e; i++) {
        float wv = __expf(g_gate[i] - m);
        accv += wv * feat[(size_t)i * DD + d];
    }
    if (e > s && sum > 0.f) out[g * DD + d] += scale * accv / sum;
}

// ---------------- launch ----------------
extern "C" void kernel_launch(void* const* d_in, const int* in_sizes, int n_in,
                              void* d_out, int out_size)
{
    const float* feat    = (const float*)d_in[0];
    const int*   src     = (const int*)d_in[1];
    const int*   dst     = (const int*)d_in[2];
    const int*   gid     = (const int*)d_in[3];
    const float* fc_w    = (const float*)d_in[4];
    const float* a_ns    = (const float*)d_in[5];
    const float* a_nd    = (const float*)d_in[6];
    const float* trans_w = (const float*)d_in[7];
    const float* trans_b = (const float*)d_in[8];
    const float* p1_w    = (const float*)d_in[9];
    const float* p1_b    = (const float*)d_in[10];
    const float* p2_w    = (const float*)d_in[11];
    const float* p2_b    = (const float*)d_in[12];
    (void)p2_b;  // per-graph softmax over gate is shift-invariant
    float* out = (float*)d_out;

    float *p_h, *p_featA, *p_featB, *p_gate, *p_sns, *p_snd;
    cudaGetSymbolAddress((void**)&p_h, g_h);
    cudaGetSymbolAddress((void**)&p_featA, g_featA);
    cudaGetSymbolAddress((void**)&p_featB, g_featB);
    cudaGetSymbolAddress((void**)&p_gate, g_gate);
    cudaGetSymbolAddress((void**)&p_sns, g_sns);
    cudaGetSymbolAddress((void**)&p_snd, g_snd);

    __nv_bfloat16 *p_fhiA, *p_floA, *p_fhiB, *p_floB, *p_agghi, *p_agglo;
    __nv_bfloat16 *p_wfchi, *p_wfclo, *p_wtrhi, *p_wtrlo, *p_wp1hi, *p_wp1lo;
    cudaGetSymbolAddress((void**)&p_fhiA, g_fhiA);
    cudaGetSymbolAddress((void**)&p_floA, g_floA);
    cudaGetSymbolAddress((void**)&p_fhiB, g_fhiB);
    cudaGetSymbolAddress((void**)&p_floB, g_floB);
    cudaGetSymbolAddress((void**)&p_agghi, g_agghi);
    cudaGetSymbolAddress((void**)&p_agglo, g_agglo);
    cudaGetSymbolAddress((void**)&p_wfchi, g_wfchi);
    cudaGetSymbolAddress((void**)&p_wfclo, g_wfclo);
    cudaGetSymbolAddress((void**)&p_wtrhi, g_wtrhi);
    cudaGetSymbolAddress((void**)&p_wtrlo, g_wtrlo);
    cudaGetSymbolAddress((void**)&p_wp1hi, g_wp1hi);
    cudaGetSymbolAddress((void**)&p_wp1lo, g_wp1lo);

    const int SMEM_GEMM = NSTAGE * STAGE_BYTES;   // 73728
    cudaFuncSetAttribute(gemm_bf16split, cudaFuncAttributeMaxDynamicSharedMemorySize, SMEM_GEMM);

    const int gx = (NN + 127) / 128;
    const int warpBlocks = (NN + 7) / 8;
    const int NCONV = LL*(HD*DD + DD*HD + TWO_D*DD);

    // launch 0: copy+split input, zero everything (incl. g_deg)
    copy_split_kernel<<<(NN * DD + 255) / 256, 256>>>(feat, out);
    // launch 1: all weight converts (+ gb_init)
    conv_all_kernel<<<(NCONV + 255) / 256, 256>>>(fc_w, trans_w, p1_w);

    // launches 2,3,4: layer-0 h-GEMM in 3 column slices (+ fused attn scores)
    for (int sl = 0; sl < 3; sl++) {
        gemm_bf16split<<<dim3(gx, 2), 256, SMEM_GEMM>>>(NN, HD, DD, sl * 128,
            p_fhiA, p_floA,
            p_wfchi + (size_t)sl * 128 * DD, p_wfclo + (size_t)sl * 128 * DD,
            (const float*)0, (const float*)0, p_h,
            (__nv_bfloat16*)0, (__nv_bfloat16*)0, 0,
            (float*)0, (const float*)0,
            p_sns, p_snd, a_ns, a_nd);
    }

    // CSR build (by dst)
    hist_kernel<<<(EE + 255) / 256, 256>>>(dst);
    scan_kernel<<<1, 1024>>>();
    scatter_kernel<<<(EE + 255) / 256, 256>>>(src, dst);
    gbounds_kernel<<<(NN + 255) / 256, 256>>>(gid);

    for (int d = 0; d < LL; d++) {
        int pp = d & 1;
        float* fin  = pp ? p_featB : p_featA;
        float* fout = pp ? p_featA : p_featB;
        __nv_bfloat16* finhi = pp ? p_fhiB : p_fhiA;
        __nv_bfloat16* finlo = pp ? p_floB : p_floA;
        __nv_bfloat16* fouthi = pp ? p_fhiA : p_fhiB;
        __nv_bfloat16* foutlo = pp ? p_floA : p_floB;

        if (d > 0) {
            zero_layer_kernel<<<(NN*HH + 255) / 256, 256>>>();
            gemm_bf16split<<<dim3(gx, HD / 64), 256, SMEM_GEMM>>>(NN, HD, DD, 0,
                finhi, finlo, p_wfchi + (size_t)d * HD * DD, p_wfclo + (size_t)d * HD * DD,
                (const float*)0, (const float*)0, p_h,
                (__nv_bfloat16*)0, (__nv_bfloat16*)0, 0,
                (float*)0, (const float*)0,
                p_sns, p_snd, a_ns + (size_t)d * HD, a_nd + (size_t)d * HD);
        }

        gat_edge_kernel<<<warpBlocks, 256>>>();

        // fout = relu?(agg @ trans_w[d]^T + b) + fin   [N, 128] (+ bf16 split out)
        gemm_bf16split<<<dim3(gx, DD / 64), 256, SMEM_GEMM>>>(NN, DD, HD, 0,
            p_agghi, p_agglo, p_wtrhi + (size_t)d * DD * HD, p_wtrlo + (size_t)d * DD * HD,
            trans_b + (size_t)d * DD, fin, fout, fouthi, foutlo, (d < LL - 1) ? 1 : 0,
            (float*)0, (const float*)0, (float*)0, (float*)0, (const float*)0, (const float*)0);

        // gate[m] = sum_n relu(fout @ p1_w[d]^T + p1_b)[m,n] * p2_w[n]
        gemm_bf16split<<<dim3(gx, TWO_D / 64), 256, SMEM_GEMM>>>(NN, TWO_D, DD, 0,
            fouthi, foutlo, p_wp1hi + (size_t)d * TWO_D * DD, p_wp1lo + (size_t)d * TWO_D * DD,
            p1_b + (size_t)d * TWO_D, (const float*)0, (float*)0,
            (__nv_bfloat16*)0, (__nv_bfloat16*)0, 1,
            p_gate, p2_w + (size_t)d * TWO_D,
            (float*)0, (float*)0, (const float*)0, (const float*)0);

        pool_kernel<<<GG, 128>>>(fout, out, 1.0f / LL);
    }
}

// round 11
// speedup vs baseline: 1.0991x; 1.0052x over previous
#include <cuda_runtime.h>
#include <cuda_bf16.h>
#include <stdint.h>
#include <math.h>

typedef unsigned int u32;

#define NN 20000
#define EE 320000
#define DD 128
#define HH 3
#define HD (HH*DD)      /* 384 */
#define LL 3
#define GG 64
#define TWO_D (2*DD)    /* 256 */
#define NEG_SLOPE 0.2f

// ---------------- scratch (device globals; no allocation allowed) ----------------
__device__ float g_h[(size_t)NN*HD];
__device__ float g_featA[(size_t)NN*DD];
__device__ float g_featB[(size_t)NN*DD];
__device__ float g_gate[NN];
__device__ float g_sns[NN*HH];
__device__ float g_snd[NN*HH];
__device__ int   g_deg[NN];
__device__ int   g_rowptr[NN+1];
__device__ int   g_cursor[NN];
__device__ int   g_csrsrc[EE];
__device__ int   g_gstart[GG];
__device__ int   g_gend[GG];

// bf16 split buffers
__device__ __nv_bfloat16 g_fhiA[(size_t)NN*DD];
__device__ __nv_bfloat16 g_floA[(size_t)NN*DD];
__device__ __nv_bfloat16 g_fhiB[(size_t)NN*DD];
__device__ __nv_bfloat16 g_floB[(size_t)NN*DD];
__device__ __nv_bfloat16 g_agghi[(size_t)NN*HD];
__device__ __nv_bfloat16 g_agglo[(size_t)NN*HD];
__device__ __nv_bfloat16 g_wfchi[(size_t)LL*HD*DD];
__device__ __nv_bfloat16 g_wfclo[(size_t)LL*HD*DD];
__device__ __nv_bfloat16 g_wtrhi[(size_t)LL*DD*HD];
__device__ __nv_bfloat16 g_wtrlo[(size_t)LL*DD*HD];
__device__ __nv_bfloat16 g_wp1hi[(size_t)LL*TWO_D*DD];
__device__ __nv_bfloat16 g_wp1lo[(size_t)LL*TWO_D*DD];

__device__ __forceinline__ void split_bf16(float v, __nv_bfloat16& hi, __nv_bfloat16& lo) {
    hi = __float2bfloat16_rn(v);
    lo = __float2bfloat16_rn(v - __bfloat162float(hi));
}

// ---------------- setup kernels ----------------
__global__ void copy_split_kernel(const float* __restrict__ srcp, float* __restrict__ out) {
    int i = blockIdx.x*blockDim.x + threadIdx.x;
    if (i < NN*DD) {
        float v = srcp[i];
        g_featA[i] = v;
        __nv_bfloat16 hi, lo; split_bf16(v, hi, lo);
        g_fhiA[i] = hi; g_floA[i] = lo;
    }
    if (i < NN*HH) { g_sns[i] = 0.f; g_snd[i] = 0.f; }
    if (i < NN)    { g_gate[i] = 0.f; g_deg[i] = 0; }
    if (i < GG*DD) out[i] = 0.f;
}

__global__ void conv_all_kernel(const float* __restrict__ fc, const float* __restrict__ tr,
                                const float* __restrict__ p1) {
    const int NFC = LL*HD*DD;
    const int NTR = LL*DD*HD;
    const int NP1 = LL*TWO_D*DD;
    int i = blockIdx.x*blockDim.x + threadIdx.x;
    if (i < NFC) {
        __nv_bfloat16 h, l; split_bf16(fc[i], h, l);
        g_wfchi[i] = h; g_wfclo[i] = l;
    } else if (i < NFC + NTR) {
        int j = i - NFC;
        __nv_bfloat16 h, l; split_bf16(tr[j], h, l);
        g_wtrhi[j] = h; g_wtrlo[j] = l;
    } else if (i < NFC + NTR + NP1) {
        int j = i - NFC - NTR;
        __nv_bfloat16 h, l; split_bf16(p1[j], h, l);
        g_wp1hi[j] = h; g_wp1lo[j] = l;
    }
    if (i < GG) { g_gstart[i] = NN; g_gend[i] = 0; }
}

__global__ void zero_layer_kernel() {
    int i = blockIdx.x*blockDim.x + threadIdx.x;
    if (i < NN*HH) { g_sns[i] = 0.f; g_snd[i] = 0.f; }
    if (i < NN)    g_gate[i] = 0.f;
}

__global__ void hist_kernel(const int* __restrict__ dst) {
    int e = blockIdx.x*blockDim.x + threadIdx.x;
    if (e < EE) atomicAdd(&g_deg[dst[e]], 1);
}

__global__ void scan_kernel() {
    __shared__ int part[1024];
    int t = threadIdx.x;
    const int CH = 20;
    int base = t * CH;
    int local[CH];
    int s = 0;
#pragma unroll
    for (int i = 0; i < CH; i++) {
        int idx = base + i;
        int v = (idx < NN) ? g_deg[idx] : 0;
        local[i] = s;
        s += v;
    }
    part[t] = s;
    __syncthreads();
    for (int off = 1; off < 1024; off <<= 1) {
        int v = (t >= off) ? part[t - off] : 0;
        __syncthreads();
        part[t] += v;
        __syncthreads();
    }
    int offset = (t > 0) ? part[t - 1] : 0;
#pragma unroll
    for (int i = 0; i < CH; i++) {
        int idx = base + i;
        if (idx < NN) {
            int r = offset + local[i];
            g_rowptr[idx] = r;
            g_cursor[idx] = r;
        }
    }
    if (t == 0) g_rowptr[NN] = part[1023];
}

__global__ void scatter_kernel(const int* __restrict__ src, const int* __restrict__ dst) {
    int e = blockIdx.x*blockDim.x + threadIdx.x;
    if (e < EE) {
        int p = atomicAdd(&g_cursor[dst[e]], 1);
        g_csrsrc[p] = src[e];
    }
}

__global__ void gbounds_kernel(const int* __restrict__ gid) {
    int i = blockIdx.x*blockDim.x + threadIdx.x;
    if (i < NN) {
        int g = gid[i];
        atomicMin(&g_gstart[g], i);
        atomicMax(&g_gend[g], i + 1);
    }
}

// ---------------- tensor-core GEMM (3-stage cp.async, swizzled smem, 1 sync/chunk) ----
// C[M, cols] = A[M,K] @ B[rows,K]^T, bf16 split: Ahi*Bhi + Ahi*Blo + Alo*Bhi
// Block tile 128x64, K-chunk 32, 256 threads (8 warps 4x2), 3 CTAs/SM.
// MMA issued term-major (8 independent accumulators between RAW chain steps).

__device__ __forceinline__ void ldm_x4(u32 addr, u32& r0, u32& r1, u32& r2, u32& r3) {
    asm volatile("ldmatrix.sync.aligned.m8n8.x4.shared.b16 {%0,%1,%2,%3}, [%4];"
        : "=r"(r0), "=r"(r1), "=r"(r2), "=r"(r3) : "r"(addr));
}

__device__ __forceinline__ void mma16816(float* c, const u32* a, const u32* b) {
    asm volatile(
        "mma.sync.aligned.m16n8k16.row.col.f32.bf16.bf16.f32 "
        "{%0,%1,%2,%3}, {%4,%5,%6,%7}, {%8,%9}, {%0,%1,%2,%3};"
        : "+f"(c[0]), "+f"(c[1]), "+f"(c[2]), "+f"(c[3])
        : "r"(a[0]), "r"(a[1]), "r"(a[2]), "r"(a[3]), "r"(b[0]), "r"(b[1]));
}

#define CP16(dst, src, sz) asm volatile( \
    "cp.async.cg.shared.global [%0], [%1], 16, %2;" :: "r"(dst), "l"(src), "r"(sz))
#define CP_COMMIT() asm volatile("cp.async.commit_group;")
#define CP_WAIT1()  asm volatile("cp.async.wait_group 1;")
#define CP_WAIT0()  asm volatile("cp.async.wait_group 0;")

#define A_BYTES (128*64)              /* 8192: 128 rows x 64B */
#define B_BYTES (64*64)               /* 4096 */
#define STAGE_BYTES (2*A_BYTES + 2*B_BYTES)   /* 24576 */
#define NSTAGE 3
#define SWZ(row, c) (((u32)(row) << 6) + (u32)(((c) ^ (((row) >> 1) & 3)) << 4))

// issue one K-chunk's copies into stage st (6 x 16B per thread)
#define GISSUE(kc, st) { \
    int kb = ((kc) << 5) + cq * 8; \
    u32 sbase = smem_u + (u32)((st) * STAGE_BYTES); \
    CP16(sbase + aoff0,                       Ahi + (size_t)arow0c * K + kb, szA0); \
    CP16(sbase + aoff0 + 4096u,               Ahi + (size_t)arow1c * K + kb, szA1); \
    CP16(sbase + (u32)A_BYTES + aoff0,        Alo + (size_t)arow0c * K + kb, szA0); \
    CP16(sbase + (u32)A_BYTES + aoff0 + 4096u, Alo + (size_t)arow1c * K + kb, szA1); \
    CP16(sbase + (u32)(2*A_BYTES) + boff,     Bhi + (size_t)(n0 + br0) * K + kb, 16); \
    CP16(sbase + (u32)(2*A_BYTES + B_BYTES) + boff, Blo + (size_t)(n0 + br0) * K + kb, 16); \
}

__global__ void __launch_bounds__(256, 3) gemm_bf16split(
    int M, int Nd, int K, int col_base,
    const __nv_bfloat16* __restrict__ Ahi, const __nv_bfloat16* __restrict__ Alo,
    const __nv_bfloat16* __restrict__ Bhi, const __nv_bfloat16* __restrict__ Blo,
    const float* __restrict__ bias, const float* __restrict__ resid,
    float* __restrict__ C, __nv_bfloat16* __restrict__ Chi, __nv_bfloat16* __restrict__ Clo,
    int do_relu,
    float* __restrict__ gatep, const float* __restrict__ p2w,
    float* __restrict__ snsp, float* __restrict__ sndp,
    const float* __restrict__ ansp, const float* __restrict__ andp)
{
    extern __shared__ __nv_bfloat16 smem[];

    const int tid  = threadIdx.x;
    const int lane = tid & 31;
    const int w    = tid >> 5;
    const int wm   = w & 3;
    const int wn   = w >> 2;
    const int m0   = blockIdx.x * 128;
    const int n0   = blockIdx.y * 64;
    const int nk   = K >> 5;

    float acc[2][4][4];
#pragma unroll
    for (int a = 0; a < 2; a++)
#pragma unroll
        for (int b = 0; b < 4; b++)
#pragma unroll
            for (int c = 0; c < 4; c++) acc[a][b][c] = 0.f;

    const u32 smem_u = (u32)__cvta_generic_to_shared(smem);

    // ldmatrix lane addressing
    const int a_row_in = (lane & 7) + ((lane >> 3) & 1) * 8;
    const int a_chalf  = lane >> 4;          // 16B column half within ks
    const int b_sub    = lane >> 3;
    const int b_row_in = (lane & 7) + (b_sub >> 1) * 8;
    const int b_chalf  = b_sub & 1;

    // per-thread copy mapping (4 threads per row, 16B each)
    const int ar0 = tid >> 2;
    const int cq  = tid & 3;                 // 16B column 0..3
    const int br0 = ar0;
    const int arow0 = m0 + ar0;
    const int arow1 = m0 + ar0 + 64;
    const int arow0c = (arow0 < M) ? arow0 : (M - 1);
    const int arow1c = (arow1 < M) ? arow1 : (M - 1);
    const u32 szA0 = (arow0 < M) ? 16u : 0u;
    const u32 szA1 = (arow1 < M) ? 16u : 0u;
    const u32 aoff0 = SWZ(ar0, cq);          // row+64 has same swizzle bits: +4096
    const u32 boff  = SWZ(br0, cq);

    // prologue: 2-deep lookahead
    GISSUE(0, 0);
    CP_COMMIT();
    if (nk > 1) { GISSUE(1, 1); CP_COMMIT(); }

    int cur = 0;
    for (int kc = 0; kc < nk; kc++) {
        if (kc + 1 < nk) { CP_WAIT1(); } else { CP_WAIT0(); }
        __syncthreads();   // stage kc visible; all warps done with stage kc-1

        const u32 stbase = smem_u + (u32)(cur * STAGE_BYTES);
#pragma unroll
        for (int ks = 0; ks < 2; ks++) {
            u32 Af[2][2][4];
            u32 Bf[2][4][2];
#pragma unroll
            for (int hl = 0; hl < 2; hl++) {
                const u32 abase = stbase + (u32)(hl * A_BYTES);
#pragma unroll
                for (int mt = 0; mt < 2; mt++) {
                    int row = wm * 32 + mt * 16 + a_row_in;
                    u32 addr = abase + SWZ(row, ks * 2 + a_chalf);
                    ldm_x4(addr, Af[hl][mt][0], Af[hl][mt][1], Af[hl][mt][2], Af[hl][mt][3]);
                }
                const u32 bbase = stbase + (u32)(2 * A_BYTES + hl * B_BYTES);
#pragma unroll
                for (int pr = 0; pr < 2; pr++) {
                    int row = wn * 32 + pr * 16 + b_row_in;
                    u32 addr2 = bbase + SWZ(row, ks * 2 + b_chalf);
                    u32 q0, q1, q2, q3;
                    ldm_x4(addr2, q0, q1, q2, q3);
                    Bf[hl][pr * 2 + 0][0] = q0; Bf[hl][pr * 2 + 0][1] = q1;
                    Bf[hl][pr * 2 + 1][0] = q2; Bf[hl][pr * 2 + 1][1] = q3;
                }
            }
            // term-major issue: 8 independent accumulators between RAW steps
#pragma unroll
            for (int term = 0; term < 3; term++) {
                const int ahl = (term == 2) ? 1 : 0;   // lo*hi uses Alo
                const int bhl = (term == 1) ? 1 : 0;   // hi*lo uses Blo
#pragma unroll
                for (int mt = 0; mt < 2; mt++)
#pragma unroll
                    for (int nt = 0; nt < 4; nt++)
                        mma16816(acc[mt][nt], Af[ahl][mt], Bf[bhl][nt]);
            }
        }

        // issue stage kc+2 into slot (kc+2)%3 == (kc-1)%3 (safe: sync above)
        if (kc + 2 < nk) {
            int st = kc + 2 - ((kc + 2) / NSTAGE) * NSTAGE;
            GISSUE(kc + 2, st);
            CP_COMMIT();
        }
        cur++; if (cur == NSTAGE) cur = 0;
    }

    // epilogue
    const int gr = lane >> 2;
    const int gc = (lane & 3) * 2;
    const int head = (col_base + n0 + wn * 32) >> 7;
#pragma unroll
    for (int mt = 0; mt < 2; mt++) {
#pragma unroll
        for (int half = 0; half < 2; half++) {
            int m = m0 + wm * 32 + mt * 16 + gr + half * 8;
            if (m >= M) continue;
            float gpart = 0.f, ps = 0.f, pt = 0.f;
#pragma unroll
            for (int nt = 0; nt < 4; nt++) {
                int gn = col_base + n0 + wn * 32 + nt * 8 + gc;
                float v0 = acc[mt][nt][half * 2 + 0];
                float v1 = acc[mt][nt][half * 2 + 1];
                if (bias) { v0 += bias[gn]; v1 += bias[gn + 1]; }
                if (do_relu) { v0 = fmaxf(v0, 0.f); v1 = fmaxf(v1, 0.f); }
                if (resid) {
                    v0 += resid[(size_t)m * Nd + gn];
                    v1 += resid[(size_t)m * Nd + gn + 1];
                }
                if (gatep) {
                    gpart += v0 * __ldg(p2w + gn) + v1 * __ldg(p2w + gn + 1);
                }
                if (snsp) {
                    ps += v0 * __ldg(ansp + gn) + v1 * __ldg(ansp + gn + 1);
                    pt += v0 * __ldg(andp + gn) + v1 * __ldg(andp + gn + 1);
                }
                if (C) {
                    float2 vv; vv.x = v0; vv.y = v1;
                    *(float2*)(C + (size_t)m * Nd + gn) = vv;
                }
                if (Chi) {
                    __nv_bfloat16 h0, l0, h1, l1;
                    split_bf16(v0, h0, l0);
                    split_bf16(v1, h1, l1);
                    __nv_bfloat162 hh; hh.x = h0; hh.y = h1;
                    __nv_bfloat162 ll; ll.x = l0; ll.y = l1;
                    *(__nv_bfloat162*)(Chi + (size_t)m * Nd + gn) = hh;
                    *(__nv_bfloat162*)(Clo + (size_t)m * Nd + gn) = ll;
                }
            }
            if (gatep) atomicAdd(gatep + m, gpart);
            if (snsp) {
                atomicAdd(snsp + m * 3 + head, ps);
                atomicAdd(sndp + m * 3 + head, pt);
            }
        }
    }
}

// ---------------- edge softmax + aggregation: one warp per dst node ----------------
__device__ __forceinline__ float leaky(float x) { return x > 0.f ? x : NEG_SLOPE * x; }

__global__ void gat_edge_kernel() {
    int v = (blockIdx.x * blockDim.x + threadIdx.x) >> 5;
    int lane = threadIdx.x & 31;
    if (v >= NN) return;
    int beg = g_rowptr[v], end = g_rowptr[v + 1];
    float snd0 = g_snd[v * 3 + 0], snd1 = g_snd[v * 3 + 1], snd2 = g_snd[v * 3 + 2];

    float m0 = -1e30f, m1 = -1e30f, m2 = -1e30f;
    for (int e = beg + lane; e < end; e += 32) {
        int s = g_csrsrc[e];
        m0 = fmaxf(m0, leaky(g_sns[s * 3 + 0] + snd0));
        m1 = fmaxf(m1, leaky(g_sns[s * 3 + 1] + snd1));
        m2 = fmaxf(m2, leaky(g_sns[s * 3 + 2] + snd2));
    }
#pragma unroll
    for (int o = 16; o; o >>= 1) {
        m0 = fmaxf(m0, __shfl_xor_sync(0xffffffffu, m0, o));
        m1 = fmaxf(m1, __shfl_xor_sync(0xffffffffu, m1, o));
        m2 = fmaxf(m2, __shfl_xor_sync(0xffffffffu, m2, o));
    }

    float acc[12];
#pragma unroll
    for (int j = 0; j < 12; j++) acc[j] = 0.f;
    float ws0 = 0.f, ws1 = 0.f, ws2 = 0.f;

    for (int e = beg; e < end; e++) {
        int s = g_csrsrc[e];
        float w0 = __expf(leaky(g_sns[s * 3 + 0] + snd0) - m0);
        float w1 = __expf(leaky(g_sns[s * 3 + 1] + snd1) - m1);
        float w2 = __expf(leaky(g_sns[s * 3 + 2] + snd2) - m2);
        ws0 += w0; ws1 += w1; ws2 += w2;
        const float* hr = g_h + (size_t)s * HD;
#pragma unroll
        for (int j = 0; j < 12; j++) {
            float wv = (j < 4) ? w0 : (j < 8) ? w1 : w2;
            acc[j] += wv * hr[j * 32 + lane];
        }
    }

    float r0 = ws0 > 0.f ? 1.f / ws0 : 0.f;
    float r1 = ws1 > 0.f ? 1.f / ws1 : 0.f;
    float r2 = ws2 > 0.f ? 1.f / ws2 : 0.f;
    __nv_bfloat16* ah = g_agghi + (size_t)v * HD;
    __nv_bfloat16* al = g_agglo + (size_t)v * HD;
#pragma unroll
    for (int j = 0; j < 12; j++) {
        float rv = (j < 4) ? r0 : (j < 8) ? r1 : r2;
        float val = acc[j] * rv;
        __nv_bfloat16 h, l; split_bf16(val, h, l);
        ah[j * 32 + lane] = h;
        al[j * 32 + lane] = l;
    }
}

// ---------------- global attention pooling ----------------
__global__ void pool_kernel(const float* __restrict__ feat, float* __restrict__ out, float scale) {
    int g = blockIdx.x;
    int d = threadIdx.x;
    int s = g_gstart[g], e = g_gend[g];
    __shared__ float red[128];

    float m = -1e30f;
    for (int i = s + d; i < e; i += 128) m = fmaxf(m, g_gate[i]);
    red[d] = m; __syncthreads();
    for (int o = 64; o; o >>= 1) { if (d < o) red[d] = fmaxf(red[d], red[d + o]); __syncthreads(); }
    m = red[0]; __syncthreads();

    float sum = 0.f;
    for (int i = s + d; i < e; i += 128) sum += __expf(g_gate[i] - m);
    red[d] = sum; __syncthreads();
    for (int o = 64; o; o >>= 1) { if (d < o) red[d] += red[d + o]; __syncthreads(); }
    sum = red[0]; __syncthreads();

    float accv = 0.f;
    for (int i = s; i < e; i++) {
        float wv = __expf(g_gate[i] - m);
        accv += wv * feat[(size_t)i * DD + d];
    }
    if (e > s && sum > 0.f) out[g * DD + d] += scale * accv / sum;
}

// ---------------- launch ----------------
extern "C" void kernel_launch(void* const* d_in, const int* in_sizes, int n_in,
                              void* d_out, int out_size)
{
    const float* feat    = (const float*)d_in[0];
    const int*   src     = (const int*)d_in[1];
    const int*   dst     = (const int*)d_in[2];
    const int*   gid     = (const int*)d_in[3];
    const float* fc_w    = (const float*)d_in[4];
    const float* a_ns    = (const float*)d_in[5];
    const float* a_nd    = (const float*)d_in[6];
    const float* trans_w = (const float*)d_in[7];
    const float* trans_b = (const float*)d_in[8];
    const float* p1_w    = (const float*)d_in[9];
    const float* p1_b    = (const float*)d_in[10];
    const float* p2_w    = (const float*)d_in[11];
    const float* p2_b    = (const float*)d_in[12];
    (void)p2_b;  // per-graph softmax over gate is shift-invariant
    float* out = (float*)d_out;

    float *p_h, *p_featA, *p_featB, *p_gate, *p_sns, *p_snd;
    cudaGetSymbolAddress((void**)&p_h, g_h);
    cudaGetSymbolAddress((void**)&p_featA, g_featA);
    cudaGetSymbolAddress((void**)&p_featB, g_featB);
    cudaGetSymbolAddress((void**)&p_gate, g_gate);
    cudaGetSymbolAddress((void**)&p_sns, g_sns);
    cudaGetSymbolAddress((void**)&p_snd, g_snd);

    __nv_bfloat16 *p_fhiA, *p_floA, *p_fhiB, *p_floB, *p_agghi, *p_agglo;
    __nv_bfloat16 *p_wfchi, *p_wfclo, *p_wtrhi, *p_wtrlo, *p_wp1hi, *p_wp1lo;
    cudaGetSymbolAddress((void**)&p_fhiA, g_fhiA);
    cudaGetSymbolAddress((void**)&p_floA, g_floA);
    cudaGetSymbolAddress((void**)&p_fhiB, g_fhiB);
    cudaGetSymbolAddress((void**)&p_floB, g_floB);
    cudaGetSymbolAddress((void**)&p_agghi, g_agghi);
    cudaGetSymbolAddress((void**)&p_agglo, g_agglo);
    cudaGetSymbolAddress((void**)&p_wfchi, g_wfchi);
    cudaGetSymbolAddress((void**)&p_wfclo, g_wfclo);
    cudaGetSymbolAddress((void**)&p_wtrhi, g_wtrhi);
    cudaGetSymbolAddress((void**)&p_wtrlo, g_wtrlo);
    cudaGetSymbolAddress((void**)&p_wp1hi, g_wp1hi);
    cudaGetSymbolAddress((void**)&p_wp1lo, g_wp1lo);

    const int SMEM_GEMM = NSTAGE * STAGE_BYTES;   // 73728
    cudaFuncSetAttribute(gemm_bf16split, cudaFuncAttributeMaxDynamicSharedMemorySize, SMEM_GEMM);

    const int gx = (NN + 127) / 128;
    const int warpBlocks = (NN + 7) / 8;
    const int NCONV = LL*(HD*DD + DD*HD + TWO_D*DD);

    // launch 0: copy+split input, zero everything (incl. g_deg)
    copy_split_kernel<<<(NN * DD + 255) / 256, 256>>>(feat, out);
    // launch 1: all weight converts (+ gb_init)
    conv_all_kernel<<<(NCONV + 255) / 256, 256>>>(fc_w, trans_w, p1_w);

    // launches 2,3,4: layer-0 h-GEMM in 3 column slices (+ fused attn scores)
    for (int sl = 0; sl < 3; sl++) {
        gemm_bf16split<<<dim3(gx, 2), 256, SMEM_GEMM>>>(NN, HD, DD, sl * 128,
            p_fhiA, p_floA,
            p_wfchi + (size_t)sl * 128 * DD, p_wfclo + (size_t)sl * 128 * DD,
            (const float*)0, (const float*)0, p_h,
            (__nv_bfloat16*)0, (__nv_bfloat16*)0, 0,
            (float*)0, (const float*)0,
            p_sns, p_snd, a_ns, a_nd);
    }

    // CSR build (by dst)
    hist_kernel<<<(EE + 255) / 256, 256>>>(dst);
    scan_kernel<<<1, 1024>>>();
    scatter_kernel<<<(EE + 255) / 256, 256>>>(src, dst);
    gbounds_kernel<<<(NN + 255) / 256, 256>>>(gid);

    for (int d = 0; d < LL; d++) {
        int pp = d & 1;
        float* fin  = pp ? p_featB : p_featA;
        float* fout = pp ? p_featA : p_featB;
        __nv_bfloat16* finhi = pp ? p_fhiB : p_fhiA;
        __nv_bfloat16* finlo = pp ? p_floB : p_floA;
        __nv_bfloat16* fouthi = pp ? p_fhiA : p_fhiB;
        __nv_bfloat16* foutlo = pp ? p_floA : p_floB;

        if (d > 0) {
            zero_layer_kernel<<<(NN*HH + 255) / 256, 256>>>();
            gemm_bf16split<<<dim3(gx, HD / 64), 256, SMEM_GEMM>>>(NN, HD, DD, 0,
                finhi, finlo, p_wfchi + (size_t)d * HD * DD, p_wfclo + (size_t)d * HD * DD,
                (const float*)0, (const float*)0, p_h,
                (__nv_bfloat16*)0, (__nv_bfloat16*)0, 0,
                (float*)0, (const float*)0,
                p_sns, p_snd, a_ns + (size_t)d * HD, a_nd + (size_t)d * HD);
        }

        gat_edge_kernel<<<warpBlocks, 256>>>();

        // fout = relu?(agg @ trans_w[d]^T + b) + fin   [N, 128] (+ bf16 split out)
        gemm_bf16split<<<dim3(gx, DD / 64), 256, SMEM_GEMM>>>(NN, DD, HD, 0,
            p_agghi, p_agglo, p_wtrhi + (size_t)d * DD * HD, p_wtrlo + (size_t)d * DD * HD,
            trans_b + (size_t)d * DD, fin, fout, fouthi, foutlo, (d < LL - 1) ? 1 : 0,
            (float*)0, (const float*)0, (float*)0, (float*)0, (const float*)0, (const float*)0);

        // gate[m] = sum_n relu(fout @ p1_w[d]^T + p1_b)[m,n] * p2_w[n]
        gemm_bf16split<<<dim3(gx, TWO_D / 64), 256, SMEM_GEMM>>>(NN, TWO_D, DD, 0,
            fouthi, foutlo, p_wp1hi + (size_t)d * TWO_D * DD, p_wp1lo + (size_t)d * TWO_D * DD,
            p1_b + (size_t)d * TWO_D, (const float*)0, (float*)0,
            (__nv_bfloat16*)0, (__nv_bfloat16*)0, 1,
            p_gate, p2_w + (size_t)d * TWO_D,
            (float*)0, (float*)0, (const float*)0, (const float*)0);

        pool_kernel<<<GG, 128>>>(fout, out, 1.0f / LL);
    }
}

// round 12
// speedup vs baseline: 1.1114x; 1.0111x over previous
#include <cuda_runtime.h>
#include <cuda_bf16.h>
#include <stdint.h>
#include <math.h>

typedef unsigned int u32;

#define NN 20000
#define EE 320000
#define DD 128
#define HH 3
#define HD (HH*DD)      /* 384 */
#define LL 3
#define GG 64
#define TWO_D (2*DD)    /* 256 */
#define NCAT (TWO_D+HD) /* 640: [p1_w(d); fc_w(d+1)] */
#define NEG_SLOPE 0.2f

// ---------------- scratch (device globals; no allocation allowed) ----------------
__device__ float g_h[(size_t)NN*HD];
__device__ float g_featA[(size_t)NN*DD];
__device__ float g_featB[(size_t)NN*DD];
__device__ float g_gate[NN];
__device__ float g_sns[NN*HH];
__device__ float g_snd[NN*HH];
__device__ int   g_deg[NN];
__device__ int   g_rowptr[NN+1];
__device__ int   g_cursor[NN];
__device__ int   g_csrsrc[EE];
__device__ int   g_gstart[GG];
__device__ int   g_gend[GG];

// bf16 split buffers
__device__ __nv_bfloat16 g_fhiA[(size_t)NN*DD];
__device__ __nv_bfloat16 g_floA[(size_t)NN*DD];
__device__ __nv_bfloat16 g_fhiB[(size_t)NN*DD];
__device__ __nv_bfloat16 g_floB[(size_t)NN*DD];
__device__ __nv_bfloat16 g_agghi[(size_t)NN*HD];
__device__ __nv_bfloat16 g_agglo[(size_t)NN*HD];
__device__ __nv_bfloat16 g_wfchi[(size_t)LL*HD*DD];
__device__ __nv_bfloat16 g_wfclo[(size_t)LL*HD*DD];
__device__ __nv_bfloat16 g_wtrhi[(size_t)LL*DD*HD];
__device__ __nv_bfloat16 g_wtrlo[(size_t)LL*DD*HD];
__device__ __nv_bfloat16 g_wcathi[(size_t)LL*NCAT*DD];
__device__ __nv_bfloat16 g_wcatlo[(size_t)LL*NCAT*DD];

__device__ __forceinline__ void split_bf16(float v, __nv_bfloat16& hi, __nv_bfloat16& lo) {
    hi = __float2bfloat16_rn(v);
    lo = __float2bfloat16_rn(v - __bfloat162float(hi));
}

// ---------------- setup kernels ----------------
// launch 0: copy+split input feat, zero everything, init graph bounds
__global__ void copy_split_kernel(const float* __restrict__ srcp, float* __restrict__ out) {
    int i = blockIdx.x*blockDim.x + threadIdx.x;
    if (i < NN*DD) {
        float v = srcp[i];
        g_featA[i] = v;
        __nv_bfloat16 hi, lo; split_bf16(v, hi, lo);
        g_fhiA[i] = hi; g_floA[i] = lo;
    }
    if (i < NN*HH) { g_sns[i] = 0.f; g_snd[i] = 0.f; }
    if (i < NN)    { g_gate[i] = 0.f; g_deg[i] = 0; }
    if (i < GG*DD) out[i] = 0.f;
    if (i < GG)    { g_gstart[i] = NN; g_gend[i] = 0; }
}

// launch 1: all weight converts (+ concat buffer) + hist + gbounds
__global__ void conv_all_kernel(const float* __restrict__ fc, const float* __restrict__ tr,
                                const float* __restrict__ p1,
                                const int* __restrict__ dst, const int* __restrict__ gid) {
    const int NFC = LL*HD*DD;
    const int NTR = LL*DD*HD;
    const int NP1 = LL*TWO_D*DD;
    int i = blockIdx.x*blockDim.x + threadIdx.x;
    if (i < NFC) {
        __nv_bfloat16 h, l; split_bf16(fc[i], h, l);
        g_wfchi[i] = h; g_wfclo[i] = l;
        int d = i / (HD*DD);
        if (d >= 1) {   // fc_w(d) also goes into Wcat(d-1) rows 256..639
            int r = i - d * (HD*DD);
            size_t ci = (size_t)(d-1) * NCAT * DD + (size_t)TWO_D * DD + r;
            g_wcathi[ci] = h; g_wcatlo[ci] = l;
        }
    } else if (i < NFC + NTR) {
        int j = i - NFC;
        __nv_bfloat16 h, l; split_bf16(tr[j], h, l);
        g_wtrhi[j] = h; g_wtrlo[j] = l;
    } else if (i < NFC + NTR + NP1) {
        int j = i - NFC - NTR;
        __nv_bfloat16 h, l; split_bf16(p1[j], h, l);
        int d = j / (TWO_D*DD);
        int r = j - d * (TWO_D*DD);
        size_t ci = (size_t)d * NCAT * DD + r;   // Wcat(d) rows 0..255
        g_wcathi[ci] = h; g_wcatlo[ci] = l;
    }
    if (i < EE) atomicAdd(&g_deg[dst[i]], 1);
    if (i < NN) {
        int g = gid[i];
        atomicMin(&g_gstart[g], i);
        atomicMax(&g_gend[g], i + 1);
    }
}

__global__ void scan_kernel() {
    __shared__ int part[1024];
    int t = threadIdx.x;
    const int CH = 20;
    int base = t * CH;
    int local[CH];
    int s = 0;
#pragma unroll
    for (int i = 0; i < CH; i++) {
        int idx = base + i;
        int v = (idx < NN) ? g_deg[idx] : 0;
        local[i] = s;
        s += v;
    }
    part[t] = s;
    __syncthreads();
    for (int off = 1; off < 1024; off <<= 1) {
        int v = (t >= off) ? part[t - off] : 0;
        __syncthreads();
        part[t] += v;
        __syncthreads();
    }
    int offset = (t > 0) ? part[t - 1] : 0;
#pragma unroll
    for (int i = 0; i < CH; i++) {
        int idx = base + i;
        if (idx < NN) {
            int r = offset + local[i];
            g_rowptr[idx] = r;
            g_cursor[idx] = r;
        }
    }
    if (t == 0) g_rowptr[NN] = part[1023];
}

__global__ void scatter_kernel(const int* __restrict__ src, const int* __restrict__ dst) {
    int e = blockIdx.x*blockDim.x + threadIdx.x;
    if (e < EE) {
        int p = atomicAdd(&g_cursor[dst[e]], 1);
        g_csrsrc[p] = src[e];
    }
}

// ---------------- tensor-core GEMM (3-stage cp.async, swizzled smem, 1 sync/chunk) ----
// C[M, cols] = A[M,K] @ B[rows,K]^T, bf16 split: Ahi*Bhi + Ahi*Blo + Alo*Bhi
// Block tile 128x64, K-chunk 32, 256 threads (8 warps 4x2), 3 CTAs/SM.
// Modes:
//   normal: bias/relu/resid/C/Chi/Clo + optional gate/sns fused epilogues
//   zero_aux: additionally zero g_sns/g_snd/g_gate per row (idempotent)
//   combined: cols<TWO_D -> gate path (p1_b bias, relu, gate atomic);
//             cols>=TWO_D -> write g_h column gn-TWO_D + attn-score atomics

__device__ __forceinline__ void ldm_x4(u32 addr, u32& r0, u32& r1, u32& r2, u32& r3) {
    asm volatile("ldmatrix.sync.aligned.m8n8.x4.shared.b16 {%0,%1,%2,%3}, [%4];"
        : "=r"(r0), "=r"(r1), "=r"(r2), "=r"(r3) : "r"(addr));
}

__device__ __forceinline__ void mma16816(float* c, const u32* a, const u32* b) {
    asm volatile(
        "mma.sync.aligned.m16n8k16.row.col.f32.bf16.bf16.f32 "
        "{%0,%1,%2,%3}, {%4,%5,%6,%7}, {%8,%9}, {%0,%1,%2,%3};"
        : "+f"(c[0]), "+f"(c[1]), "+f"(c[2]), "+f"(c[3])
        : "r"(a[0]), "r"(a[1]), "r"(a[2]), "r"(a[3]), "r"(b[0]), "r"(b[1]));
}

#define CP16(dst, src, sz) asm volatile( \
    "cp.async.cg.shared.global [%0], [%1], 16, %2;" :: "r"(dst), "l"(src), "r"(sz))
#define CP_COMMIT() asm volatile("cp.async.commit_group;")
#define CP_WAIT1()  asm volatile("cp.async.wait_group 1;")
#define CP_WAIT0()  asm volatile("cp.async.wait_group 0;")

#define A_BYTES (128*64)              /* 8192: 128 rows x 64B */
#define B_BYTES (64*64)               /* 4096 */
#define STAGE_BYTES (2*A_BYTES + 2*B_BYTES)   /* 24576 */
#define NSTAGE 3
#define SWZ(row, c) (((u32)(row) << 6) + (u32)(((c) ^ (((row) >> 1) & 3)) << 4))

#define GISSUE(kc, st) { \
    int kb = ((kc) << 5) + cq * 8; \
    u32 sbase = smem_u + (u32)((st) * STAGE_BYTES); \
    CP16(sbase + aoff0,                       Ahi + (size_t)arow0c * K + kb, szA0); \
    CP16(sbase + aoff0 + 4096u,               Ahi + (size_t)arow1c * K + kb, szA1); \
    CP16(sbase + (u32)A_BYTES + aoff0,        Alo + (size_t)arow0c * K + kb, szA0); \
    CP16(sbase + (u32)A_BYTES + aoff0 + 4096u, Alo + (size_t)arow1c * K + kb, szA1); \
    CP16(sbase + (u32)(2*A_BYTES) + boff,     Bhi + (size_t)(n0 + br0) * K + kb, 16); \
    CP16(sbase + (u32)(2*A_BYTES + B_BYTES) + boff, Blo + (size_t)(n0 + br0) * K + kb, 16); \
}

__global__ void __launch_bounds__(256, 3) gemm_bf16split(
    int M, int Nd, int K, int col_base,
    const __nv_bfloat16* __restrict__ Ahi, const __nv_bfloat16* __restrict__ Alo,
    const __nv_bfloat16* __restrict__ Bhi, const __nv_bfloat16* __restrict__ Blo,
    const float* __restrict__ bias, const float* __restrict__ resid,
    float* __restrict__ C, __nv_bfloat16* __restrict__ Chi, __nv_bfloat16* __restrict__ Clo,
    int do_relu,
    float* __restrict__ gatep, const float* __restrict__ p2w,
    float* __restrict__ snsp, float* __restrict__ sndp,
    const float* __restrict__ ansp, const float* __restrict__ andp,
    int combined, int zero_aux)
{
    extern __shared__ __nv_bfloat16 smem[];

    const int tid  = threadIdx.x;
    const int lane = tid & 31;
    const int w    = tid >> 5;
    const int wm   = w & 3;
    const int wn   = w >> 2;
    const int m0   = blockIdx.x * 128;
    const int n0   = blockIdx.y * 64;
    const int nk   = K >> 5;

    float acc[2][4][4];
#pragma unroll
    for (int a = 0; a < 2; a++)
#pragma unroll
        for (int b = 0; b < 4; b++)
#pragma unroll
            for (int c = 0; c < 4; c++) acc[a][b][c] = 0.f;

    const u32 smem_u = (u32)__cvta_generic_to_shared(smem);

    const int a_row_in = (lane & 7) + ((lane >> 3) & 1) * 8;
    const int a_chalf  = lane >> 4;
    const int b_sub    = lane >> 3;
    const int b_row_in = (lane & 7) + (b_sub >> 1) * 8;
    const int b_chalf  = b_sub & 1;

    const int ar0 = tid >> 2;
    const int cq  = tid & 3;
    const int br0 = ar0;
    const int arow0 = m0 + ar0;
    const int arow1 = m0 + ar0 + 64;
    const int arow0c = (arow0 < M) ? arow0 : (M - 1);
    const int arow1c = (arow1 < M) ? arow1 : (M - 1);
    const u32 szA0 = (arow0 < M) ? 16u : 0u;
    const u32 szA1 = (arow1 < M) ? 16u : 0u;
    const u32 aoff0 = SWZ(ar0, cq);
    const u32 boff  = SWZ(br0, cq);

    GISSUE(0, 0);
    CP_COMMIT();
    if (nk > 1) { GISSUE(1, 1); CP_COMMIT(); }

    int cur = 0;
    for (int kc = 0; kc < nk; kc++) {
        if (kc + 1 < nk) { CP_WAIT1(); } else { CP_WAIT0(); }
        __syncthreads();

        const u32 stbase = smem_u + (u32)(cur * STAGE_BYTES);
#pragma unroll
        for (int ks = 0; ks < 2; ks++) {
            u32 Af[2][2][4];
            u32 Bf[2][4][2];
#pragma unroll
            for (int hl = 0; hl < 2; hl++) {
                const u32 abase = stbase + (u32)(hl * A_BYTES);
#pragma unroll
                for (int mt = 0; mt < 2; mt++) {
                    int row = wm * 32 + mt * 16 + a_row_in;
                    u32 addr = abase + SWZ(row, ks * 2 + a_chalf);
                    ldm_x4(addr, Af[hl][mt][0], Af[hl][mt][1], Af[hl][mt][2], Af[hl][mt][3]);
                }
                const u32 bbase = stbase + (u32)(2 * A_BYTES + hl * B_BYTES);
#pragma unroll
                for (int pr = 0; pr < 2; pr++) {
                    int row = wn * 32 + pr * 16 + b_row_in;
                    u32 addr2 = bbase + SWZ(row, ks * 2 + b_chalf);
                    u32 q0, q1, q2, q3;
                    ldm_x4(addr2, q0, q1, q2, q3);
                    Bf[hl][pr * 2 + 0][0] = q0; Bf[hl][pr * 2 + 0][1] = q1;
                    Bf[hl][pr * 2 + 1][0] = q2; Bf[hl][pr * 2 + 1][1] = q3;
                }
            }
#pragma unroll
            for (int term = 0; term < 3; term++) {
                const int ahl = (term == 2) ? 1 : 0;
                const int bhl = (term == 1) ? 1 : 0;
#pragma unroll
                for (int mt = 0; mt < 2; mt++)
#pragma unroll
                    for (int nt = 0; nt < 4; nt++)
                        mma16816(acc[mt][nt], Af[ahl][mt], Bf[bhl][nt]);
            }
        }

        if (kc + 2 < nk) {
            int st = kc + 2 - ((kc + 2) / NSTAGE) * NSTAGE;
            GISSUE(kc + 2, st);
            CP_COMMIT();
        }
        cur++; if (cur == NSTAGE) cur = 0;
    }

    // epilogue
    const int gr = lane >> 2;
    const int gc = (lane & 3) * 2;
    const int wspan = col_base + n0 + wn * 32;      // warp-uniform column base
    const bool isGate = wspan < TWO_D;              // combined-mode region
    const int head = combined ? ((wspan - TWO_D) >> 7) : (wspan >> 7);
#pragma unroll
    for (int mt = 0; mt < 2; mt++) {
#pragma unroll
        for (int half = 0; half < 2; half++) {
            int m = m0 + wm * 32 + mt * 16 + gr + half * 8;
            if (m >= M) continue;
            float gpart = 0.f, ps = 0.f, pt = 0.f;
#pragma unroll
            for (int nt = 0; nt < 4; nt++) {
                int gn = col_base + n0 + wn * 32 + nt * 8 + gc;
                float v0 = acc[mt][nt][half * 2 + 0];
                float v1 = acc[mt][nt][half * 2 + 1];
                if (combined) {
                    if (isGate) {
                        v0 += bias[gn]; v1 += bias[gn + 1];
                        v0 = fmaxf(v0, 0.f); v1 = fmaxf(v1, 0.f);
                        gpart += v0 * __ldg(p2w + gn) + v1 * __ldg(p2w + gn + 1);
                    } else {
                        int hc = gn - TWO_D;
                        ps += v0 * __ldg(ansp + hc) + v1 * __ldg(ansp + hc + 1);
                        pt += v0 * __ldg(andp + hc) + v1 * __ldg(andp + hc + 1);
                        float2 vv; vv.x = v0; vv.y = v1;
                        *(float2*)(g_h + (size_t)m * HD + hc) = vv;
                    }
                    continue;
                }
                if (bias) { v0 += bias[gn]; v1 += bias[gn + 1]; }
                if (do_relu) { v0 = fmaxf(v0, 0.f); v1 = fmaxf(v1, 0.f); }
                if (resid) {
                    v0 += resid[(size_t)m * Nd + gn];
                    v1 += resid[(size_t)m * Nd + gn + 1];
                }
                if (gatep) {
                    gpart += v0 * __ldg(p2w + gn) + v1 * __ldg(p2w + gn + 1);
                }
                if (snsp) {
                    ps += v0 * __ldg(ansp + gn) + v1 * __ldg(ansp + gn + 1);
                    pt += v0 * __ldg(andp + gn) + v1 * __ldg(andp + gn + 1);
                }
                if (C) {
                    float2 vv; vv.x = v0; vv.y = v1;
                    *(float2*)(C + (size_t)m * Nd + gn) = vv;
                }
                if (Chi) {
                    __nv_bfloat16 h0, l0, h1, l1;
                    split_bf16(v0, h0, l0);
                    split_bf16(v1, h1, l1);
                    __nv_bfloat162 hh; hh.x = h0; hh.y = h1;
                    __nv_bfloat162 ll; ll.x = l0; ll.y = l1;
                    *(__nv_bfloat162*)(Chi + (size_t)m * Nd + gn) = hh;
                    *(__nv_bfloat162*)(Clo + (size_t)m * Nd + gn) = ll;
                }
            }
            if (combined) {
                if (isGate) atomicAdd(gatep + m, gpart);
                else {
                    atomicAdd(snsp + m * 3 + head, ps);
                    atomicAdd(sndp + m * 3 + head, pt);
                }
            } else {
                if (gatep) atomicAdd(gatep + m, gpart);
                if (snsp) {
                    atomicAdd(snsp + m * 3 + head, ps);
                    atomicAdd(sndp + m * 3 + head, pt);
                }
            }
            if (zero_aux) {   // idempotent zeroes for next launch's atomics
                g_sns[m * 3 + 0] = 0.f; g_sns[m * 3 + 1] = 0.f; g_sns[m * 3 + 2] = 0.f;
                g_snd[m * 3 + 0] = 0.f; g_snd[m * 3 + 1] = 0.f; g_snd[m * 3 + 2] = 0.f;
                g_gate[m] = 0.f;
            }
        }
    }
}

// ---------------- edge softmax + aggregation: one warp per dst node ----------------
__device__ __forceinline__ float leaky(float x) { return x > 0.f ? x : NEG_SLOPE * x; }

__global__ void gat_edge_kernel() {
    int v = (blockIdx.x * blockDim.x + threadIdx.x) >> 5;
    int lane = threadIdx.x & 31;
    if (v >= NN) return;
    int beg = g_rowptr[v], end = g_rowptr[v + 1];
    float snd0 = g_snd[v * 3 + 0], snd1 = g_snd[v * 3 + 1], snd2 = g_snd[v * 3 + 2];

    float m0 = -1e30f, m1 = -1e30f, m2 = -1e30f;
    for (int e = beg + lane; e < end; e += 32) {
        int s = g_csrsrc[e];
        m0 = fmaxf(m0, leaky(g_sns[s * 3 + 0] + snd0));
        m1 = fmaxf(m1, leaky(g_sns[s * 3 + 1] + snd1));
        m2 = fmaxf(m2, leaky(g_sns[s * 3 + 2] + snd2));
    }
#pragma unroll
    for (int o = 16; o; o >>= 1) {
        m0 = fmaxf(m0, __shfl_xor_sync(0xffffffffu, m0, o));
        m1 = fmaxf(m1, __shfl_xor_sync(0xffffffffu, m1, o));
        m2 = fmaxf(m2, __shfl_xor_sync(0xffffffffu, m2, o));
    }

    float acc[12];
#pragma unroll
    for (int j = 0; j < 12; j++) acc[j] = 0.f;
    float ws0 = 0.f, ws1 = 0.f, ws2 = 0.f;

    for (int e = beg; e < end; e++) {
        int s = g_csrsrc[e];
        float w0 = __expf(leaky(g_sns[s * 3 + 0] + snd0) - m0);
        float w1 = __expf(leaky(g_sns[s * 3 + 1] + snd1) - m1);
        float w2 = __expf(leaky(g_sns[s * 3 + 2] + snd2) - m2);
        ws0 += w0; ws1 += w1; ws2 += w2;
        const float* hr = g_h + (size_t)s * HD;
#pragma unroll
        for (int j = 0; j < 12; j++) {
            float wv = (j < 4) ? w0 : (j < 8) ? w1 : w2;
            acc[j] += wv * hr[j * 32 + lane];
        }
    }

    float r0 = ws0 > 0.f ? 1.f / ws0 : 0.f;
    float r1 = ws1 > 0.f ? 1.f / ws1 : 0.f;
    float r2 = ws2 > 0.f ? 1.f / ws2 : 0.f;
    __nv_bfloat16* ah = g_agghi + (size_t)v * HD;
    __nv_bfloat16* al = g_agglo + (size_t)v * HD;
#pragma unroll
    for (int j = 0; j < 12; j++) {
        float rv = (j < 4) ? r0 : (j < 8) ? r1 : r2;
        float val = acc[j] * rv;
        __nv_bfloat16 h, l; split_bf16(val, h, l);
        ah[j * 32 + lane] = h;
        al[j * 32 + lane] = l;
    }
}

// ---------------- global attention pooling ----------------
__global__ void pool_kernel(const float* __restrict__ feat, float* __restrict__ out, float scale) {
    int g = blockIdx.x;
    int d = threadIdx.x;
    int s = g_gstart[g], e = g_gend[g];
    __shared__ float red[128];

    float m = -1e30f;
    for (int i = s + d; i < e; i += 128) m = fmaxf(m, g_gate[i]);
    red[d] = m; __syncthreads();
    for (int o = 64; o; o >>= 1) { if (d < o) red[d] = fmaxf(red[d], red[d + o]); __syncthreads(); }
    m = red[0]; __syncthreads();

    float sum = 0.f;
    for (int i = s + d; i < e; i += 128) sum += __expf(g_gate[i] - m);
    red[d] = sum; __syncthreads();
    for (int o = 64; o; o >>= 1) { if (d < o) red[d] += red[d + o]; __syncthreads(); }
    sum = red[0]; __syncthreads();

    float accv = 0.f;
    for (int i = s; i < e; i++) {
        float wv = __expf(g_gate[i] - m);
        accv += wv * feat[(size_t)i * DD + d];
    }
    if (e > s && sum > 0.f) out[g * DD + d] += scale * accv / sum;
}

// ---------------- launch ----------------
extern "C" void kernel_launch(void* const* d_in, const int* in_sizes, int n_in,
                              void* d_out, int out_size)
{
    const float* feat    = (const float*)d_in[0];
    const int*   src     = (const int*)d_in[1];
    const int*   dst     = (const int*)d_in[2];
    const int*   gid     = (const int*)d_in[3];
    const float* fc_w    = (const float*)d_in[4];
    const float* a_ns    = (const float*)d_in[5];
    const float* a_nd    = (const float*)d_in[6];
    const float* trans_w = (const float*)d_in[7];
    const float* trans_b = (const float*)d_in[8];
    const float* p1_w    = (const float*)d_in[9];
    const float* p1_b    = (const float*)d_in[10];
    const float* p2_w    = (const float*)d_in[11];
    const float* p2_b    = (const float*)d_in[12];
    (void)p2_b;  // per-graph softmax over gate is shift-invariant
    float* out = (float*)d_out;

    float *p_h, *p_featA, *p_featB, *p_gate, *p_sns, *p_snd;
    cudaGetSymbolAddress((void**)&p_h, g_h);
    cudaGetSymbolAddress((void**)&p_featA, g_featA);
    cudaGetSymbolAddress((void**)&p_featB, g_featB);
    cudaGetSymbolAddress((void**)&p_gate, g_gate);
    cudaGetSymbolAddress((void**)&p_sns, g_sns);
    cudaGetSymbolAddress((void**)&p_snd, g_snd);

    __nv_bfloat16 *p_fhiA, *p_floA, *p_fhiB, *p_floB, *p_agghi, *p_agglo;
    __nv_bfloat16 *p_wfchi, *p_wfclo, *p_wtrhi, *p_wtrlo, *p_wcathi, *p_wcatlo;
    cudaGetSymbolAddress((void**)&p_fhiA, g_fhiA);
    cudaGetSymbolAddress((void**)&p_floA, g_floA);
    cudaGetSymbolAddress((void**)&p_fhiB, g_fhiB);
    cudaGetSymbolAddress((void**)&p_floB, g_floB);
    cudaGetSymbolAddress((void**)&p_agghi, g_agghi);
    cudaGetSymbolAddress((void**)&p_agglo, g_agglo);
    cudaGetSymbolAddress((void**)&p_wfchi, g_wfchi);
    cudaGetSymbolAddress((void**)&p_wfclo, g_wfclo);
    cudaGetSymbolAddress((void**)&p_wtrhi, g_wtrhi);
    cudaGetSymbolAddress((void**)&p_wtrlo, g_wtrlo);
    cudaGetSymbolAddress((void**)&p_wcathi, g_wcathi);
    cudaGetSymbolAddress((void**)&p_wcatlo, g_wcatlo);

    const int SMEM_GEMM = NSTAGE * STAGE_BYTES;   // 73728
    cudaFuncSetAttribute(gemm_bf16split, cudaFuncAttributeMaxDynamicSharedMemorySize, SMEM_GEMM);

    const int gx = (NN + 127) / 128;
    const int warpBlocks = (NN + 7) / 8;
    const int NCONV = LL*(HD*DD + DD*HD + TWO_D*DD);

    // launch 0: copy+split input, zero everything, init graph bounds
    copy_split_kernel<<<(NN * DD + 255) / 256, 256>>>(feat, out);
    // launch 1: weight converts + concat + hist + gbounds
    conv_all_kernel<<<(NCONV + 255) / 256, 256>>>(fc_w, trans_w, p1_w, dst, gid);

    // launches 2,3,4: layer-0 h-GEMM in 3 column slices (+ fused attn scores)
    for (int sl = 0; sl < 3; sl++) {
        gemm_bf16split<<<dim3(gx, 2), 256, SMEM_GEMM>>>(NN, HD, DD, sl * 128,
            p_fhiA, p_floA,
            p_wfchi + (size_t)sl * 128 * DD, p_wfclo + (size_t)sl * 128 * DD,
            (const float*)0, (const float*)0, p_h,
            (__nv_bfloat16*)0, (__nv_bfloat16*)0, 0,
            (float*)0, (const float*)0,
            p_sns, p_snd, a_ns, a_nd, 0, 0);
    }

    // CSR build (by dst)
    scan_kernel<<<1, 1024>>>();
    scatter_kernel<<<(EE + 255) / 256, 256>>>(src, dst);

    for (int d = 0; d < LL; d++) {
        int pp = d & 1;
        float* fin  = pp ? p_featB : p_featA;
        float* fout = pp ? p_featA : p_featB;
        __nv_bfloat16* fouthi = pp ? p_fhiA : p_fhiB;
        __nv_bfloat16* foutlo = pp ? p_floA : p_floB;

        gat_edge_kernel<<<warpBlocks, 256>>>();

        // fout = relu?(agg @ trans_w[d]^T + b) + fin  (+ bf16 split out, + zero aux)
        gemm_bf16split<<<dim3(gx, DD / 64), 256, SMEM_GEMM>>>(NN, DD, HD, 0,
            p_agghi, p_agglo, p_wtrhi + (size_t)d * DD * HD, p_wtrlo + (size_t)d * DD * HD,
            trans_b + (size_t)d * DD, fin, fout, fouthi, foutlo, (d < LL - 1) ? 1 : 0,
            (float*)0, (const float*)0, (float*)0, (float*)0, (const float*)0, (const float*)0,
            0, 1);

        // combined: gate GEMM (cols 0..255) + next layer's h-GEMM (cols 256..639)
        int yB = (d < LL - 1) ? (NCAT / 64) : (TWO_D / 64);
        int dn = (d < LL - 1) ? (d + 1) : d;   // ans offset for h region (unused when d=LL-1)
        gemm_bf16split<<<dim3(gx, yB), 256, SMEM_GEMM>>>(NN, HD, DD, 0,
            fouthi, foutlo,
            p_wcathi + (size_t)d * NCAT * DD, p_wcatlo + (size_t)d * NCAT * DD,
            p1_b + (size_t)d * TWO_D, (const float*)0, (float*)0,
            (__nv_bfloat16*)0, (__nv_bfloat16*)0, 0,
            p_gate, p2_w + (size_t)d * TWO_D,
            p_sns, p_snd, a_ns + (size_t)dn * HD, a_nd + (size_t)dn * HD,
            1, 0);

        pool_kernel<<<GG, 128>>>(fout, out, 1.0f / LL);
    }
}

// round 13
// speedup vs baseline: 1.1387x; 1.0246x over previous
#include <cuda_runtime.h>
#include <cuda_bf16.h>
#include <stdint.h>
#include <math.h>

typedef unsigned int u32;

#define NN 20000
#define EE 320000
#define DD 128
#define HH 3
#define HD (HH*DD)      /* 384 */
#define LL 3
#define GG 64
#define TWO_D (2*DD)    /* 256 */
#define NCAT (TWO_D+HD) /* 640: [p1_w(d); fc_w(d+1)] */
#define NEG_SLOPE 0.2f

// ---------------- scratch (device globals; no allocation allowed) ----------------
__device__ float g_h[(size_t)NN*HD];
__device__ float g_featA[(size_t)NN*DD];
__device__ float g_featB[(size_t)NN*DD];
__device__ float g_gate[NN];
__device__ float g_sns[NN*HH];
__device__ float g_snd[NN*HH];
__device__ int   g_deg[NN];
__device__ int   g_rowptr[NN+1];
__device__ int   g_cursor[NN];
__device__ int   g_csrsrc[EE];
__device__ int   g_gstart[GG];
__device__ int   g_gend[GG];

// bf16 split buffers
__device__ __nv_bfloat16 g_fhiA[(size_t)NN*DD];
__device__ __nv_bfloat16 g_floA[(size_t)NN*DD];
__device__ __nv_bfloat16 g_fhiB[(size_t)NN*DD];
__device__ __nv_bfloat16 g_floB[(size_t)NN*DD];
__device__ __nv_bfloat16 g_agghi[(size_t)NN*HD];
__device__ __nv_bfloat16 g_agglo[(size_t)NN*HD];
__device__ __nv_bfloat16 g_wfchi[(size_t)LL*HD*DD];
__device__ __nv_bfloat16 g_wfclo[(size_t)LL*HD*DD];
__device__ __nv_bfloat16 g_wtrhi[(size_t)LL*DD*HD];
__device__ __nv_bfloat16 g_wtrlo[(size_t)LL*DD*HD];
__device__ __nv_bfloat16 g_wcathi[(size_t)LL*NCAT*DD];
__device__ __nv_bfloat16 g_wcatlo[(size_t)LL*NCAT*DD];

__device__ __forceinline__ void split_bf16(float v, __nv_bfloat16& hi, __nv_bfloat16& lo) {
    hi = __float2bfloat16_rn(v);
    lo = __float2bfloat16_rn(v - __bfloat162float(hi));
}

// ---------------- setup kernels ----------------
__global__ void copy_split_kernel(const float* __restrict__ srcp, float* __restrict__ out) {
    int i = blockIdx.x*blockDim.x + threadIdx.x;
    if (i < NN*DD) {
        float v = srcp[i];
        g_featA[i] = v;
        __nv_bfloat16 hi, lo; split_bf16(v, hi, lo);
        g_fhiA[i] = hi; g_floA[i] = lo;
    }
    if (i < NN*HH) { g_sns[i] = 0.f; g_snd[i] = 0.f; }
    if (i < NN)    { g_gate[i] = 0.f; g_deg[i] = 0; }
    if (i < GG*DD) out[i] = 0.f;
    if (i < GG)    { g_gstart[i] = NN; g_gend[i] = 0; }
}

__global__ void conv_all_kernel(const float* __restrict__ fc, const float* __restrict__ tr,
                                const float* __restrict__ p1,
                                const int* __restrict__ dst, const int* __restrict__ gid) {
    const int NFC = LL*HD*DD;
    const int NTR = LL*DD*HD;
    const int NP1 = LL*TWO_D*DD;
    int i = blockIdx.x*blockDim.x + threadIdx.x;
    if (i < NFC) {
        __nv_bfloat16 h, l; split_bf16(fc[i], h, l);
        g_wfchi[i] = h; g_wfclo[i] = l;
        int d = i / (HD*DD);
        if (d >= 1) {
            int r = i - d * (HD*DD);
            size_t ci = (size_t)(d-1) * NCAT * DD + (size_t)TWO_D * DD + r;
            g_wcathi[ci] = h; g_wcatlo[ci] = l;
        }
    } else if (i < NFC + NTR) {
        int j = i - NFC;
        __nv_bfloat16 h, l; split_bf16(tr[j], h, l);
        g_wtrhi[j] = h; g_wtrlo[j] = l;
    } else if (i < NFC + NTR + NP1) {
        int j = i - NFC - NTR;
        __nv_bfloat16 h, l; split_bf16(p1[j], h, l);
        int d = j / (TWO_D*DD);
        int r = j - d * (TWO_D*DD);
        size_t ci = (size_t)d * NCAT * DD + r;
        g_wcathi[ci] = h; g_wcatlo[ci] = l;
    }
    if (i < EE) atomicAdd(&g_deg[dst[i]], 1);
    if (i < NN) {
        int g = gid[i];
        atomicMin(&g_gstart[g], i);
        atomicMax(&g_gend[g], i + 1);
    }
}

__global__ void scan_kernel() {
    __shared__ int part[1024];
    int t = threadIdx.x;
    const int CH = 20;
    int base = t * CH;
    int local[CH];
    int s = 0;
#pragma unroll
    for (int i = 0; i < CH; i++) {
        int idx = base + i;
        int v = (idx < NN) ? g_deg[idx] : 0;
        local[i] = s;
        s += v;
    }
    part[t] = s;
    __syncthreads();
    for (int off = 1; off < 1024; off <<= 1) {
        int v = (t >= off) ? part[t - off] : 0;
        __syncthreads();
        part[t] += v;
        __syncthreads();
    }
    int offset = (t > 0) ? part[t - 1] : 0;
#pragma unroll
    for (int i = 0; i < CH; i++) {
        int idx = base + i;
        if (idx < NN) {
            int r = offset + local[i];
            g_rowptr[idx] = r;
            g_cursor[idx] = r;
        }
    }
    if (t == 0) g_rowptr[NN] = part[1023];
}

__global__ void scatter_kernel(const int* __restrict__ src, const int* __restrict__ dst) {
    int e = blockIdx.x*blockDim.x + threadIdx.x;
    if (e < EE) {
        int p = atomicAdd(&g_cursor[dst[e]], 1);
        g_csrsrc[p] = src[e];
    }
}

// ---------------- tensor-core GEMM (3-stage cp.async, swizzled smem, 1 sync/chunk) ----
// C[M, cols] = A[M,K] @ B[rows,K]^T, bf16 split: Ahi*Bhi + Ahi*Blo + Alo*Bhi
// Block tile 128x64, K-chunk 32, 256 threads (8 warps 4x2), 3 CTAs/SM.
// Next-stage cp.async issued immediately after the barrier (full overlap).

__device__ __forceinline__ void ldm_x4(u32 addr, u32& r0, u32& r1, u32& r2, u32& r3) {
    asm volatile("ldmatrix.sync.aligned.m8n8.x4.shared.b16 {%0,%1,%2,%3}, [%4];"
        : "=r"(r0), "=r"(r1), "=r"(r2), "=r"(r3) : "r"(addr));
}

__device__ __forceinline__ void mma16816(float* c, const u32* a, const u32* b) {
    asm volatile(
        "mma.sync.aligned.m16n8k16.row.col.f32.bf16.bf16.f32 "
        "{%0,%1,%2,%3}, {%4,%5,%6,%7}, {%8,%9}, {%0,%1,%2,%3};"
        : "+f"(c[0]), "+f"(c[1]), "+f"(c[2]), "+f"(c[3])
        : "r"(a[0]), "r"(a[1]), "r"(a[2]), "r"(a[3]), "r"(b[0]), "r"(b[1]));
}

#define CP16(dst, src, sz) asm volatile( \
    "cp.async.cg.shared.global [%0], [%1], 16, %2;" :: "r"(dst), "l"(src), "r"(sz))
#define CP_COMMIT() asm volatile("cp.async.commit_group;")
#define CP_WAIT1()  asm volatile("cp.async.wait_group 1;")
#define CP_WAIT0()  asm volatile("cp.async.wait_group 0;")

#define A_BYTES (128*64)
#define B_BYTES (64*64)
#define STAGE_BYTES (2*A_BYTES + 2*B_BYTES)   /* 24576 */
#define NSTAGE 3
#define SWZ(row, c) (((u32)(row) << 6) + (u32)(((c) ^ (((row) >> 1) & 3)) << 4))

#define GISSUE(kc, st) { \
    int kb = ((kc) << 5) + cq * 8; \
    u32 sbase = smem_u + (u32)((st) * STAGE_BYTES); \
    CP16(sbase + aoff0,                       Ahi + (size_t)arow0c * K + kb, szA0); \
    CP16(sbase + aoff0 + 4096u,               Ahi + (size_t)arow1c * K + kb, szA1); \
    CP16(sbase + (u32)A_BYTES + aoff0,        Alo + (size_t)arow0c * K + kb, szA0); \
    CP16(sbase + (u32)A_BYTES + aoff0 + 4096u, Alo + (size_t)arow1c * K + kb, szA1); \
    CP16(sbase + (u32)(2*A_BYTES) + boff,     Bhi + (size_t)(n0 + br0) * K + kb, 16); \
    CP16(sbase + (u32)(2*A_BYTES + B_BYTES) + boff, Blo + (size_t)(n0 + br0) * K + kb, 16); \
}

__global__ void __launch_bounds__(256, 3) gemm_bf16split(
    int M, int Nd, int K, int col_base,
    const __nv_bfloat16* __restrict__ Ahi, const __nv_bfloat16* __restrict__ Alo,
    const __nv_bfloat16* __restrict__ Bhi, const __nv_bfloat16* __restrict__ Blo,
    const float* __restrict__ bias, const float* __restrict__ resid,
    float* __restrict__ C, __nv_bfloat16* __restrict__ Chi, __nv_bfloat16* __restrict__ Clo,
    int do_relu,
    float* __restrict__ gatep, const float* __restrict__ p2w,
    float* __restrict__ snsp, float* __restrict__ sndp,
    const float* __restrict__ ansp, const float* __restrict__ andp,
    int combined, int zero_aux)
{
    extern __shared__ __nv_bfloat16 smem[];

    const int tid  = threadIdx.x;
    const int lane = tid & 31;
    const int w    = tid >> 5;
    const int wm   = w & 3;
    const int wn   = w >> 2;
    const int m0   = blockIdx.x * 128;
    const int n0   = blockIdx.y * 64;
    const int nk   = K >> 5;

    float acc[2][4][4];
#pragma unroll
    for (int a = 0; a < 2; a++)
#pragma unroll
        for (int b = 0; b < 4; b++)
#pragma unroll
            for (int c = 0; c < 4; c++) acc[a][b][c] = 0.f;

    const u32 smem_u = (u32)__cvta_generic_to_shared(smem);

    const int a_row_in = (lane & 7) + ((lane >> 3) & 1) * 8;
    const int a_chalf  = lane >> 4;
    const int b_sub    = lane >> 3;
    const int b_row_in = (lane & 7) + (b_sub >> 1) * 8;
    const int b_chalf  = b_sub & 1;

    const int ar0 = tid >> 2;
    const int cq  = tid & 3;
    const int br0 = ar0;
    const int arow0 = m0 + ar0;
    const int arow1 = m0 + ar0 + 64;
    const int arow0c = (arow0 < M) ? arow0 : (M - 1);
    const int arow1c = (arow1 < M) ? arow1 : (M - 1);
    const u32 szA0 = (arow0 < M) ? 16u : 0u;
    const u32 szA1 = (arow1 < M) ? 16u : 0u;
    const u32 aoff0 = SWZ(ar0, cq);
    const u32 boff  = SWZ(br0, cq);

    GISSUE(0, 0);
    CP_COMMIT();
    if (nk > 1) { GISSUE(1, 1); CP_COMMIT(); }

    int cur = 0;
    for (int kc = 0; kc < nk; kc++) {
        if (kc + 1 < nk) { CP_WAIT1(); } else { CP_WAIT0(); }
        __syncthreads();   // stage kc visible; all warps done with stage kc-1

        // issue stage kc+2 into slot (kc-1)%3 BEFORE compute: full overlap
        if (kc + 2 < nk) {
            int st = kc + 2 - ((kc + 2) / NSTAGE) * NSTAGE;
            GISSUE(kc + 2, st);
            CP_COMMIT();
        }

        const u32 stbase = smem_u + (u32)(cur * STAGE_BYTES);
#pragma unroll
        for (int ks = 0; ks < 2; ks++) {
            u32 Af[2][2][4];
            u32 Bf[2][4][2];
#pragma unroll
            for (int hl = 0; hl < 2; hl++) {
                const u32 abase = stbase + (u32)(hl * A_BYTES);
#pragma unroll
                for (int mt = 0; mt < 2; mt++) {
                    int row = wm * 32 + mt * 16 + a_row_in;
                    u32 addr = abase + SWZ(row, ks * 2 + a_chalf);
                    ldm_x4(addr, Af[hl][mt][0], Af[hl][mt][1], Af[hl][mt][2], Af[hl][mt][3]);
                }
                const u32 bbase = stbase + (u32)(2 * A_BYTES + hl * B_BYTES);
#pragma unroll
                for (int pr = 0; pr < 2; pr++) {
                    int row = wn * 32 + pr * 16 + b_row_in;
                    u32 addr2 = bbase + SWZ(row, ks * 2 + b_chalf);
                    u32 q0, q1, q2, q3;
                    ldm_x4(addr2, q0, q1, q2, q3);
                    Bf[hl][pr * 2 + 0][0] = q0; Bf[hl][pr * 2 + 0][1] = q1;
                    Bf[hl][pr * 2 + 1][0] = q2; Bf[hl][pr * 2 + 1][1] = q3;
                }
            }
#pragma unroll
            for (int term = 0; term < 3; term++) {
                const int ahl = (term == 2) ? 1 : 0;
                const int bhl = (term == 1) ? 1 : 0;
#pragma unroll
                for (int mt = 0; mt < 2; mt++)
#pragma unroll
                    for (int nt = 0; nt < 4; nt++)
                        mma16816(acc[mt][nt], Af[ahl][mt], Bf[bhl][nt]);
            }
        }
        cur++; if (cur == NSTAGE) cur = 0;
    }

    // epilogue
    const int gr = lane >> 2;
    const int gc = (lane & 3) * 2;
    const int wspan = col_base + n0 + wn * 32;
    const bool isGate = wspan < TWO_D;
    const int head = combined ? ((wspan - TWO_D) >> 7) : (wspan >> 7);
#pragma unroll
    for (int mt = 0; mt < 2; mt++) {
#pragma unroll
        for (int half = 0; half < 2; half++) {
            int m = m0 + wm * 32 + mt * 16 + gr + half * 8;
            if (m >= M) continue;
            float gpart = 0.f, ps = 0.f, pt = 0.f;
#pragma unroll
            for (int nt = 0; nt < 4; nt++) {
                int gn = col_base + n0 + wn * 32 + nt * 8 + gc;
                float v0 = acc[mt][nt][half * 2 + 0];
                float v1 = acc[mt][nt][half * 2 + 1];
                if (combined) {
                    if (isGate) {
                        v0 += bias[gn]; v1 += bias[gn + 1];
                        v0 = fmaxf(v0, 0.f); v1 = fmaxf(v1, 0.f);
                        gpart += v0 * __ldg(p2w + gn) + v1 * __ldg(p2w + gn + 1);
                    } else {
                        int hc = gn - TWO_D;
                        ps += v0 * __ldg(ansp + hc) + v1 * __ldg(ansp + hc + 1);
                        pt += v0 * __ldg(andp + hc) + v1 * __ldg(andp + hc + 1);
                        float2 vv; vv.x = v0; vv.y = v1;
                        *(float2*)(g_h + (size_t)m * HD + hc) = vv;
                    }
                    continue;
                }
                if (bias) { v0 += bias[gn]; v1 += bias[gn + 1]; }
                if (do_relu) { v0 = fmaxf(v0, 0.f); v1 = fmaxf(v1, 0.f); }
                if (resid) {
                    v0 += resid[(size_t)m * Nd + gn];
                    v1 += resid[(size_t)m * Nd + gn + 1];
                }
                if (gatep) {
                    gpart += v0 * __ldg(p2w + gn) + v1 * __ldg(p2w + gn + 1);
                }
                if (snsp) {
                    ps += v0 * __ldg(ansp + gn) + v1 * __ldg(ansp + gn + 1);
                    pt += v0 * __ldg(andp + gn) + v1 * __ldg(andp + gn + 1);
                }
                if (C) {
                    float2 vv; vv.x = v0; vv.y = v1;
                    *(float2*)(C + (size_t)m * Nd + gn) = vv;
                }
                if (Chi) {
                    __nv_bfloat16 h0, l0, h1, l1;
                    split_bf16(v0, h0, l0);
                    split_bf16(v1, h1, l1);
                    __nv_bfloat162 hh; hh.x = h0; hh.y = h1;
                    __nv_bfloat162 ll; ll.x = l0; ll.y = l1;
                    *(__nv_bfloat162*)(Chi + (size_t)m * Nd + gn) = hh;
                    *(__nv_bfloat162*)(Clo + (size_t)m * Nd + gn) = ll;
                }
            }
            if (combined) {
                if (isGate) atomicAdd(gatep + m, gpart);
                else {
                    atomicAdd(snsp + m * 3 + head, ps);
                    atomicAdd(sndp + m * 3 + head, pt);
                }
            } else {
                if (gatep) atomicAdd(gatep + m, gpart);
                if (snsp) {
                    atomicAdd(snsp + m * 3 + head, ps);
                    atomicAdd(sndp + m * 3 + head, pt);
                }
            }
            if (zero_aux) {
                g_sns[m * 3 + 0] = 0.f; g_sns[m * 3 + 1] = 0.f; g_sns[m * 3 + 2] = 0.f;
                g_snd[m * 3 + 0] = 0.f; g_snd[m * 3 + 1] = 0.f; g_snd[m * 3 + 2] = 0.f;
                g_gate[m] = 0.f;
            }
        }
    }
}

// ---------------- edge softmax + aggregation: one warp per dst node ----------------
__device__ __forceinline__ float leaky(float x) { return x > 0.f ? x : NEG_SLOPE * x; }

__global__ void gat_edge_kernel() {
    int v = (blockIdx.x * blockDim.x + threadIdx.x) >> 5;
    int lane = threadIdx.x & 31;
    if (v >= NN) return;
    int beg = g_rowptr[v], end = g_rowptr[v + 1];
    float snd0 = g_snd[v * 3 + 0], snd1 = g_snd[v * 3 + 1], snd2 = g_snd[v * 3 + 2];

    float m0 = -1e30f, m1 = -1e30f, m2 = -1e30f;
    for (int e = beg + lane; e < end; e += 32) {
        int s = g_csrsrc[e];
        m0 = fmaxf(m0, leaky(g_sns[s * 3 + 0] + snd0));
        m1 = fmaxf(m1, leaky(g_sns[s * 3 + 1] + snd1));
        m2 = fmaxf(m2, leaky(g_sns[s * 3 + 2] + snd2));
    }
#pragma unroll
    for (int o = 16; o; o >>= 1) {
        m0 = fmaxf(m0, __shfl_xor_sync(0xffffffffu, m0, o));
        m1 = fmaxf(m1, __shfl_xor_sync(0xffffffffu, m1, o));
        m2 = fmaxf(m2, __shfl_xor_sync(0xffffffffu, m2, o));
    }

    float acc[12];
#pragma unroll
    for (int j = 0; j < 12; j++) acc[j] = 0.f;
    float ws0 = 0.f, ws1 = 0.f, ws2 = 0.f;

    for (int e = beg; e < end; e++) {
        int s = g_csrsrc[e];
        float w0 = __expf(leaky(g_sns[s * 3 + 0] + snd0) - m0);
        float w1 = __expf(leaky(g_sns[s * 3 + 1] + snd1) - m1);
        float w2 = __expf(leaky(g_sns[s * 3 + 2] + snd2) - m2);
        ws0 += w0; ws1 += w1; ws2 += w2;
        const float* hr = g_h + (size_t)s * HD;
#pragma unroll
        for (int j = 0; j < 12; j++) {
            float wv = (j < 4) ? w0 : (j < 8) ? w1 : w2;
            acc[j] += wv * hr[j * 32 + lane];
        }
    }

    float r0 = ws0 > 0.f ? 1.f / ws0 : 0.f;
    float r1 = ws1 > 0.f ? 1.f / ws1 : 0.f;
    float r2 = ws2 > 0.f ? 1.f / ws2 : 0.f;
    __nv_bfloat16* ah = g_agghi + (size_t)v * HD;
    __nv_bfloat16* al = g_agglo + (size_t)v * HD;
#pragma unroll
    for (int j = 0; j < 12; j++) {
        float rv = (j < 4) ? r0 : (j < 8) ? r1 : r2;
        float val = acc[j] * rv;
        __nv_bfloat16 h, l; split_bf16(val, h, l);
        ah[j * 32 + lane] = h;
        al[j * 32 + lane] = l;
    }
}

// ---------------- global attention pooling ----------------
__global__ void pool_kernel(const float* __restrict__ feat, float* __restrict__ out, float scale) {
    int g = blockIdx.x;
    int d = threadIdx.x;
    int s = g_gstart[g], e = g_gend[g];
    __shared__ float red[128];

    float m = -1e30f;
    for (int i = s + d; i < e; i += 128) m = fmaxf(m, g_gate[i]);
    red[d] = m; __syncthreads();
    for (int o = 64; o; o >>= 1) { if (d < o) red[d] = fmaxf(red[d], red[d + o]); __syncthreads(); }
    m = red[0]; __syncthreads();

    float sum = 0.f;
    for (int i = s + d; i < e; i += 128) sum += __expf(g_gate[i] - m);
    red[d] = sum; __syncthreads();
    for (int o = 64; o; o >>= 1) { if (d < o) red[d] += red[d + o]; __syncthreads(); }
    sum = red[0]; __syncthreads();

    float accv = 0.f;
    for (int i = s; i < e; i++) {
        float wv = __expf(g_gate[i] - m);
        accv += wv * feat[(size_t)i * DD + d];
    }
    if (e > s && sum > 0.f) out[g * DD + d] += scale * accv / sum;
}

// ---------------- launch ----------------
extern "C" void kernel_launch(void* const* d_in, const int* in_sizes, int n_in,
                              void* d_out, int out_size)
{
    const float* feat    = (const float*)d_in[0];
    const int*   src     = (const int*)d_in[1];
    const int*   dst     = (const int*)d_in[2];
    const int*   gid     = (const int*)d_in[3];
    const float* fc_w    = (const float*)d_in[4];
    const float* a_ns    = (const float*)d_in[5];
    const float* a_nd    = (const float*)d_in[6];
    const float* trans_w = (const float*)d_in[7];
    const float* trans_b = (const float*)d_in[8];
    const float* p1_w    = (const float*)d_in[9];
    const float* p1_b    = (const float*)d_in[10];
    const float* p2_w    = (const float*)d_in[11];
    const float* p2_b    = (const float*)d_in[12];
    (void)p2_b;  // per-graph softmax over gate is shift-invariant
    float* out = (float*)d_out;

    float *p_h, *p_featA, *p_featB, *p_gate, *p_sns, *p_snd;
    cudaGetSymbolAddress((void**)&p_h, g_h);
    cudaGetSymbolAddress((void**)&p_featA, g_featA);
    cudaGetSymbolAddress((void**)&p_featB, g_featB);
    cudaGetSymbolAddress((void**)&p_gate, g_gate);
    cudaGetSymbolAddress((void**)&p_sns, g_sns);
    cudaGetSymbolAddress((void**)&p_snd, g_snd);

    __nv_bfloat16 *p_fhiA, *p_floA, *p_fhiB, *p_floB, *p_agghi, *p_agglo;
    __nv_bfloat16 *p_wfchi, *p_wfclo, *p_wtrhi, *p_wtrlo, *p_wcathi, *p_wcatlo;
    cudaGetSymbolAddress((void**)&p_fhiA, g_fhiA);
    cudaGetSymbolAddress((void**)&p_floA, g_floA);
    cudaGetSymbolAddress((void**)&p_fhiB, g_fhiB);
    cudaGetSymbolAddress((void**)&p_floB, g_floB);
    cudaGetSymbolAddress((void**)&p_agghi, g_agghi);
    cudaGetSymbolAddress((void**)&p_agglo, g_agglo);
    cudaGetSymbolAddress((void**)&p_wfchi, g_wfchi);
    cudaGetSymbolAddress((void**)&p_wfclo, g_wfclo);
    cudaGetSymbolAddress((void**)&p_wtrhi, g_wtrhi);
    cudaGetSymbolAddress((void**)&p_wtrlo, g_wtrlo);
    cudaGetSymbolAddress((void**)&p_wcathi, g_wcathi);
    cudaGetSymbolAddress((void**)&p_wcatlo, g_wcatlo);

    const int SMEM_GEMM = NSTAGE * STAGE_BYTES;   // 73728
    cudaFuncSetAttribute(gemm_bf16split, cudaFuncAttributeMaxDynamicSharedMemorySize, SMEM_GEMM);

    const int gx = (NN + 127) / 128;
    const int warpBlocks = (NN + 7) / 8;
    const int NCONV = LL*(HD*DD + DD*HD + TWO_D*DD);

    // launch 0: copy+split input, zero everything, init graph bounds
    copy_split_kernel<<<(NN * DD + 255) / 256, 256>>>(feat, out);
    // launch 1: weight converts + concat + hist + gbounds
    conv_all_kernel<<<(NCONV + 255) / 256, 256>>>(fc_w, trans_w, p1_w, dst, gid);

    // launch 2: layer-0 h-GEMM, all 384 columns in one launch (+ fused attn scores)
    gemm_bf16split<<<dim3(gx, HD / 64), 256, SMEM_GEMM>>>(NN, HD, DD, 0,
        p_fhiA, p_floA, p_wfchi, p_wfclo,
        (const float*)0, (const float*)0, p_h,
        (__nv_bfloat16*)0, (__nv_bfloat16*)0, 0,
        (float*)0, (const float*)0,
        p_sns, p_snd, a_ns, a_nd, 0, 0);

    // CSR build (by dst)
    scan_kernel<<<1, 1024>>>();
    scatter_kernel<<<(EE + 255) / 256, 256>>>(src, dst);

    for (int d = 0; d < LL; d++) {
        int pp = d & 1;
        float* fin  = pp ? p_featB : p_featA;
        float* fout = pp ? p_featA : p_featB;
        __nv_bfloat16* fouthi = pp ? p_fhiA : p_fhiB;
        __nv_bfloat16* foutlo = pp ? p_floA : p_floB;

        gat_edge_kernel<<<warpBlocks, 256>>>();

        // fout = relu?(agg @ trans_w[d]^T + b) + fin  (+ bf16 split out, + zero aux)
        gemm_bf16split<<<dim3(gx, DD / 64), 256, SMEM_GEMM>>>(NN, DD, HD, 0,
            p_agghi, p_agglo, p_wtrhi + (size_t)d * DD * HD, p_wtrlo + (size_t)d * DD * HD,
            trans_b + (size_t)d * DD, fin, fout, fouthi, foutlo, (d < LL - 1) ? 1 : 0,
            (float*)0, (const float*)0, (float*)0, (float*)0, (const float*)0, (const float*)0,
            0, 1);

        // combined: gate GEMM (cols 0..255) + next layer's h-GEMM (cols 256..639)
        int yB = (d < LL - 1) ? (NCAT / 64) : (TWO_D / 64);
        int dn = (d < LL - 1) ? (d + 1) : d;
        gemm_bf16split<<<dim3(gx, yB), 256, SMEM_GEMM>>>(NN, HD, DD, 0,
            fouthi, foutlo,
            p_wcathi + (size_t)d * NCAT * DD, p_wcatlo + (size_t)d * NCAT * DD,
            p1_b + (size_t)d * TWO_D, (const float*)0, (float*)0,
            (__nv_bfloat16*)0, (__nv_bfloat16*)0, 0,
            p_gate, p2_w + (size_t)d * TWO_D,
            p_sns, p_snd, a_ns + (size_t)dn * HD, a_nd + (size_t)dn * HD,
            1, 0);

        pool_kernel<<<GG, 128>>>(fout, out, 1.0f / LL);
    }
}

// round 14
// speedup vs baseline: 1.1618x; 1.0203x over previous
#include <cuda_runtime.h>
#include <cuda_bf16.h>
#include <stdint.h>
#include <math.h>

typedef unsigned int u32;

#define NN 20000
#define EE 320000
#define DD 128
#define HH 3
#define HD (HH*DD)      /* 384 */
#define LL 3
#define GG 64
#define TWO_D (2*DD)    /* 256 */
#define NCAT (TWO_D+HD) /* 640: [p1_w(d); fc_w(d+1)] */
#define NEG_SLOPE 0.2f

// ---------------- scratch (device globals; no allocation allowed) ----------------
__device__ float g_h[(size_t)NN*HD];
__device__ float g_featA[(size_t)NN*DD];
__device__ float g_featB[(size_t)NN*DD];
__device__ float g_gate[NN];
__device__ float g_sns[NN*HH];
__device__ float g_snd[NN*HH];
__device__ int   g_deg[NN];
__device__ int   g_rowptr[NN+1];
__device__ int   g_cursor[NN];
__device__ int   g_csrsrc[EE];
__device__ int   g_gstart[GG];
__device__ int   g_gend[GG];

// bf16 split buffers
__device__ __nv_bfloat16 g_fhiA[(size_t)NN*DD];
__device__ __nv_bfloat16 g_floA[(size_t)NN*DD];
__device__ __nv_bfloat16 g_fhiB[(size_t)NN*DD];
__device__ __nv_bfloat16 g_floB[(size_t)NN*DD];
__device__ __nv_bfloat16 g_agghi[(size_t)NN*HD];
__device__ __nv_bfloat16 g_agglo[(size_t)NN*HD];
__device__ __nv_bfloat16 g_wfchi[(size_t)LL*HD*DD];
__device__ __nv_bfloat16 g_wfclo[(size_t)LL*HD*DD];
__device__ __nv_bfloat16 g_wtrhi[(size_t)LL*DD*HD];
__device__ __nv_bfloat16 g_wtrlo[(size_t)LL*DD*HD];
__device__ __nv_bfloat16 g_wcathi[(size_t)LL*NCAT*DD];
__device__ __nv_bfloat16 g_wcatlo[(size_t)LL*NCAT*DD];

__device__ __forceinline__ void split_bf16(float v, __nv_bfloat16& hi, __nv_bfloat16& lo) {
    hi = __float2bfloat16_rn(v);
    lo = __float2bfloat16_rn(v - __bfloat162float(hi));
}

// ---------------- setup kernels ----------------
__global__ void copy_split_kernel(const float* __restrict__ srcp, float* __restrict__ out) {
    int i = blockIdx.x*blockDim.x + threadIdx.x;
    if (i < NN*DD) {
        float v = srcp[i];
        g_featA[i] = v;
        __nv_bfloat16 hi, lo; split_bf16(v, hi, lo);
        g_fhiA[i] = hi; g_floA[i] = lo;
    }
    if (i < NN*HH) { g_sns[i] = 0.f; g_snd[i] = 0.f; }
    if (i < NN)    { g_gate[i] = 0.f; g_deg[i] = 0; }
    if (i < GG*DD) out[i] = 0.f;
    if (i < GG)    { g_gstart[i] = NN; g_gend[i] = 0; }
}

__global__ void conv_all_kernel(const float* __restrict__ fc, const float* __restrict__ tr,
                                const float* __restrict__ p1,
                                const int* __restrict__ dst, const int* __restrict__ gid) {
    const int NFC = LL*HD*DD;
    const int NTR = LL*DD*HD;
    const int NP1 = LL*TWO_D*DD;
    int i = blockIdx.x*blockDim.x + threadIdx.x;
    if (i < NFC) {
        __nv_bfloat16 h, l; split_bf16(fc[i], h, l);
        g_wfchi[i] = h; g_wfclo[i] = l;
        int d = i / (HD*DD);
        if (d >= 1) {
            int r = i - d * (HD*DD);
            size_t ci = (size_t)(d-1) * NCAT * DD + (size_t)TWO_D * DD + r;
            g_wcathi[ci] = h; g_wcatlo[ci] = l;
        }
    } else if (i < NFC + NTR) {
        int j = i - NFC;
        __nv_bfloat16 h, l; split_bf16(tr[j], h, l);
        g_wtrhi[j] = h; g_wtrlo[j] = l;
    } else if (i < NFC + NTR + NP1) {
        int j = i - NFC - NTR;
        __nv_bfloat16 h, l; split_bf16(p1[j], h, l);
        int d = j / (TWO_D*DD);
        int r = j - d * (TWO_D*DD);
        size_t ci = (size_t)d * NCAT * DD + r;
        g_wcathi[ci] = h; g_wcatlo[ci] = l;
    }
    if (i < EE) atomicAdd(&g_deg[dst[i]], 1);
    if (i < NN) {
        int g = gid[i];
        atomicMin(&g_gstart[g], i);
        atomicMax(&g_gend[g], i + 1);
    }
}

// ---- single-block prefix scan, smem-staged, coalesced IO ----
#define SCAN_CH 20
#define SCAN_SMEM ((NN + 1024) * (int)sizeof(int))   /* 84096 B */
__global__ void scan_kernel() {
    extern __shared__ int sm[];
    int* vals = sm;            // NN entries
    int* part = sm + NN;       // 1024 partials
    const int t = threadIdx.x;

    // coalesced load g_deg -> smem
    for (int j = t; j < NN; j += 1024) vals[j] = g_deg[j];
    __syncthreads();

    // per-thread chunk: replace with exclusive prefix, keep chunk sum
    const int base = t * SCAN_CH;
    int s = 0;
#pragma unroll
    for (int i = 0; i < SCAN_CH; i++) {
        int idx = base + i;
        if (idx < NN) {
            int v = vals[idx];
            vals[idx] = s;
            s += v;
        }
    }
    part[t] = s;
    __syncthreads();

    // Hillis-Steele over 1024 partials (inclusive)
    for (int off = 1; off < 1024; off <<= 1) {
        int v = (t >= off) ? part[t - off] : 0;
        __syncthreads();
        part[t] += v;
        __syncthreads();
    }

    // coalesced writes: rowptr/cursor = chunk-exclusive + within-chunk exclusive
    for (int j = t; j < NN; j += 1024) {
        int c = j / SCAN_CH;
        int off = (c > 0) ? part[c - 1] : 0;
        int r = off + vals[j];
        g_rowptr[j] = r;
        g_cursor[j] = r;
    }
    if (t == 0) g_rowptr[NN] = part[1023];
}

__global__ void scatter_kernel(const int* __restrict__ src, const int* __restrict__ dst) {
    int e = blockIdx.x*blockDim.x + threadIdx.x;
    if (e < EE) {
        int p = atomicAdd(&g_cursor[dst[e]], 1);
        g_csrsrc[p] = src[e];
    }
}

// ---------------- tensor-core GEMM (3-stage cp.async, swizzled smem, 1 sync/chunk) ----
__device__ __forceinline__ void ldm_x4(u32 addr, u32& r0, u32& r1, u32& r2, u32& r3) {
    asm volatile("ldmatrix.sync.aligned.m8n8.x4.shared.b16 {%0,%1,%2,%3}, [%4];"
        : "=r"(r0), "=r"(r1), "=r"(r2), "=r"(r3) : "r"(addr));
}

__device__ __forceinline__ void mma16816(float* c, const u32* a, const u32* b) {
    asm volatile(
        "mma.sync.aligned.m16n8k16.row.col.f32.bf16.bf16.f32 "
        "{%0,%1,%2,%3}, {%4,%5,%6,%7}, {%8,%9}, {%0,%1,%2,%3};"
        : "+f"(c[0]), "+f"(c[1]), "+f"(c[2]), "+f"(c[3])
        : "r"(a[0]), "r"(a[1]), "r"(a[2]), "r"(a[3]), "r"(b[0]), "r"(b[1]));
}

#define CP16(dst, src, sz) asm volatile( \
    "cp.async.cg.shared.global [%0], [%1], 16, %2;" :: "r"(dst), "l"(src), "r"(sz))
#define CP_COMMIT() asm volatile("cp.async.commit_group;")
#define CP_WAIT1()  asm volatile("cp.async.wait_group 1;")
#define CP_WAIT0()  asm volatile("cp.async.wait_group 0;")

#define A_BYTES (128*64)
#define B_BYTES (64*64)
#define STAGE_BYTES (2*A_BYTES + 2*B_BYTES)   /* 24576 */
#define NSTAGE 3
#define SWZ(row, c) (((u32)(row) << 6) + (u32)(((c) ^ (((row) >> 1) & 3)) << 4))

#define GISSUE(kc, st) { \
    int kb = ((kc) << 5) + cq * 8; \
    u32 sbase = smem_u + (u32)((st) * STAGE_BYTES); \
    CP16(sbase + aoff0,                       Ahi + (size_t)arow0c * K + kb, szA0); \
    CP16(sbase + aoff0 + 4096u,               Ahi + (size_t)arow1c * K + kb, szA1); \
    CP16(sbase + (u32)A_BYTES + aoff0,        Alo + (size_t)arow0c * K + kb, szA0); \
    CP16(sbase + (u32)A_BYTES + aoff0 + 4096u, Alo + (size_t)arow1c * K + kb, szA1); \
    CP16(sbase + (u32)(2*A_BYTES) + boff,     Bhi + (size_t)(n0 + br0) * K + kb, 16); \
    CP16(sbase + (u32)(2*A_BYTES + B_BYTES) + boff, Blo + (size_t)(n0 + br0) * K + kb, 16); \
}

__global__ void __launch_bounds__(256, 3) gemm_bf16split(
    int M, int Nd, int K, int col_base,
    const __nv_bfloat16* __restrict__ Ahi, const __nv_bfloat16* __restrict__ Alo,
    const __nv_bfloat16* __restrict__ Bhi, const __nv_bfloat16* __restrict__ Blo,
    const float* __restrict__ bias, const float* __restrict__ resid,
    float* __restrict__ C, __nv_bfloat16* __restrict__ Chi, __nv_bfloat16* __restrict__ Clo,
    int do_relu,
    float* __restrict__ gatep, const float* __restrict__ p2w,
    float* __restrict__ snsp, float* __restrict__ sndp,
    const float* __restrict__ ansp, const float* __restrict__ andp,
    int combined, int zero_aux)
{
    extern __shared__ __nv_bfloat16 smem[];

    const int tid  = threadIdx.x;
    const int lane = tid & 31;
    const int w    = tid >> 5;
    const int wm   = w & 3;
    const int wn   = w >> 2;
    const int m0   = blockIdx.x * 128;
    const int n0   = blockIdx.y * 64;
    const int nk   = K >> 5;

    float acc[2][4][4];
#pragma unroll
    for (int a = 0; a < 2; a++)
#pragma unroll
        for (int b = 0; b < 4; b++)
#pragma unroll
            for (int c = 0; c < 4; c++) acc[a][b][c] = 0.f;

    const u32 smem_u = (u32)__cvta_generic_to_shared(smem);

    const int a_row_in = (lane & 7) + ((lane >> 3) & 1) * 8;
    const int a_chalf  = lane >> 4;
    const int b_sub    = lane >> 3;
    const int b_row_in = (lane & 7) + (b_sub >> 1) * 8;
    const int b_chalf  = b_sub & 1;

    const int ar0 = tid >> 2;
    const int cq  = tid & 3;
    const int br0 = ar0;
    const int arow0 = m0 + ar0;
    const int arow1 = m0 + ar0 + 64;
    const int arow0c = (arow0 < M) ? arow0 : (M - 1);
    const int arow1c = (arow1 < M) ? arow1 : (M - 1);
    const u32 szA0 = (arow0 < M) ? 16u : 0u;
    const u32 szA1 = (arow1 < M) ? 16u : 0u;
    const u32 aoff0 = SWZ(ar0, cq);
    const u32 boff  = SWZ(br0, cq);

    GISSUE(0, 0);
    CP_COMMIT();
    if (nk > 1) { GISSUE(1, 1); CP_COMMIT(); }

    int cur = 0;
    for (int kc = 0; kc < nk; kc++) {
        if (kc + 1 < nk) { CP_WAIT1(); } else { CP_WAIT0(); }
        __syncthreads();

        if (kc + 2 < nk) {
            int st = kc + 2 - ((kc + 2) / NSTAGE) * NSTAGE;
            GISSUE(kc + 2, st);
            CP_COMMIT();
        }

        const u32 stbase = smem_u + (u32)(cur * STAGE_BYTES);
#pragma unroll
        for (int ks = 0; ks < 2; ks++) {
            u32 Af[2][2][4];
            u32 Bf[2][4][2];
#pragma unroll
            for (int hl = 0; hl < 2; hl++) {
                const u32 abase = stbase + (u32)(hl * A_BYTES);
#pragma unroll
                for (int mt = 0; mt < 2; mt++) {
                    int row = wm * 32 + mt * 16 + a_row_in;
                    u32 addr = abase + SWZ(row, ks * 2 + a_chalf);
                    ldm_x4(addr, Af[hl][mt][0], Af[hl][mt][1], Af[hl][mt][2], Af[hl][mt][3]);
                }
                const u32 bbase = stbase + (u32)(2 * A_BYTES + hl * B_BYTES);
#pragma unroll
                for (int pr = 0; pr < 2; pr++) {
                    int row = wn * 32 + pr * 16 + b_row_in;
                    u32 addr2 = bbase + SWZ(row, ks * 2 + b_chalf);
                    u32 q0, q1, q2, q3;
                    ldm_x4(addr2, q0, q1, q2, q3);
                    Bf[hl][pr * 2 + 0][0] = q0; Bf[hl][pr * 2 + 0][1] = q1;
                    Bf[hl][pr * 2 + 1][0] = q2; Bf[hl][pr * 2 + 1][1] = q3;
                }
            }
#pragma unroll
            for (int term = 0; term < 3; term++) {
                const int ahl = (term == 2) ? 1 : 0;
                const int bhl = (term == 1) ? 1 : 0;
#pragma unroll
                for (int mt = 0; mt < 2; mt++)
#pragma unroll
                    for (int nt = 0; nt < 4; nt++)
                        mma16816(acc[mt][nt], Af[ahl][mt], Bf[bhl][nt]);
            }
        }
        cur++; if (cur == NSTAGE) cur = 0;
    }

    // epilogue
    const int gr = lane >> 2;
    const int gc = (lane & 3) * 2;
    const int wspan = col_base + n0 + wn * 32;
    const bool isGate = wspan < TWO_D;
    const int head = combined ? ((wspan - TWO_D) >> 7) : (wspan >> 7);
#pragma unroll
    for (int mt = 0; mt < 2; mt++) {
#pragma unroll
        for (int half = 0; half < 2; half++) {
            int m = m0 + wm * 32 + mt * 16 + gr + half * 8;
            if (m >= M) continue;
            float gpart = 0.f, ps = 0.f, pt = 0.f;
#pragma unroll
            for (int nt = 0; nt < 4; nt++) {
                int gn = col_base + n0 + wn * 32 + nt * 8 + gc;
                float v0 = acc[mt][nt][half * 2 + 0];
                float v1 = acc[mt][nt][half * 2 + 1];
                if (combined) {
                    if (isGate) {
                        v0 += bias[gn]; v1 += bias[gn + 1];
                        v0 = fmaxf(v0, 0.f); v1 = fmaxf(v1, 0.f);
                        gpart += v0 * __ldg(p2w + gn) + v1 * __ldg(p2w + gn + 1);
                    } else {
                        int hc = gn - TWO_D;
                        ps += v0 * __ldg(ansp + hc) + v1 * __ldg(ansp + hc + 1);
                        pt += v0 * __ldg(andp + hc) + v1 * __ldg(andp + hc + 1);
                        float2 vv; vv.x = v0; vv.y = v1;
                        *(float2*)(g_h + (size_t)m * HD + hc) = vv;
                    }
                    continue;
                }
                if (bias) { v0 += bias[gn]; v1 += bias[gn + 1]; }
                if (do_relu) { v0 = fmaxf(v0, 0.f); v1 = fmaxf(v1, 0.f); }
                if (resid) {
                    v0 += resid[(size_t)m * Nd + gn];
                    v1 += resid[(size_t)m * Nd + gn + 1];
                }
                if (gatep) {
                    gpart += v0 * __ldg(p2w + gn) + v1 * __ldg(p2w + gn + 1);
                }
                if (snsp) {
                    ps += v0 * __ldg(ansp + gn) + v1 * __ldg(ansp + gn + 1);
                    pt += v0 * __ldg(andp + gn) + v1 * __ldg(andp + gn + 1);
                }
                if (C) {
                    float2 vv; vv.x = v0; vv.y = v1;
                    *(float2*)(C + (size_t)m * Nd + gn) = vv;
                }
                if (Chi) {
                    __nv_bfloat16 h0, l0, h1, l1;
                    split_bf16(v0, h0, l0);
                    split_bf16(v1, h1, l1);
                    __nv_bfloat162 hh; hh.x = h0; hh.y = h1;
                    __nv_bfloat162 ll; ll.x = l0; ll.y = l1;
                    *(__nv_bfloat162*)(Chi + (size_t)m * Nd + gn) = hh;
                    *(__nv_bfloat162*)(Clo + (size_t)m * Nd + gn) = ll;
                }
            }
            if (combined) {
                if (isGate) atomicAdd(gatep + m, gpart);
                else {
                    atomicAdd(snsp + m * 3 + head, ps);
                    atomicAdd(sndp + m * 3 + head, pt);
                }
            } else {
                if (gatep) atomicAdd(gatep + m, gpart);
                if (snsp) {
                    atomicAdd(snsp + m * 3 + head, ps);
                    atomicAdd(sndp + m * 3 + head, pt);
                }
            }
            if (zero_aux) {
                g_sns[m * 3 + 0] = 0.f; g_sns[m * 3 + 1] = 0.f; g_sns[m * 3 + 2] = 0.f;
                g_snd[m * 3 + 0] = 0.f; g_snd[m * 3 + 1] = 0.f; g_snd[m * 3 + 2] = 0.f;
                g_gate[m] = 0.f;
            }
        }
    }
}

// ---------------- edge softmax + aggregation: one warp per dst node ----------------
__device__ __forceinline__ float leaky(float x) { return x > 0.f ? x : NEG_SLOPE * x; }

__global__ void gat_edge_kernel() {
    int v = (blockIdx.x * blockDim.x + threadIdx.x) >> 5;
    int lane = threadIdx.x & 31;
    if (v >= NN) return;
    int beg = g_rowptr[v], end = g_rowptr[v + 1];
    float snd0 = g_snd[v * 3 + 0], snd1 = g_snd[v * 3 + 1], snd2 = g_snd[v * 3 + 2];

    float m0 = -1e30f, m1 = -1e30f, m2 = -1e30f;
    for (int e = beg + lane; e < end; e += 32) {
        int s = g_csrsrc[e];
        m0 = fmaxf(m0, leaky(g_sns[s * 3 + 0] + snd0));
        m1 = fmaxf(m1, leaky(g_sns[s * 3 + 1] + snd1));
        m2 = fmaxf(m2, leaky(g_sns[s * 3 + 2] + snd2));
    }
#pragma unroll
    for (int o = 16; o; o >>= 1) {
        m0 = fmaxf(m0, __shfl_xor_sync(0xffffffffu, m0, o));
        m1 = fmaxf(m1, __shfl_xor_sync(0xffffffffu, m1, o));
        m2 = fmaxf(m2, __shfl_xor_sync(0xffffffffu, m2, o));
    }

    float acc[12];
#pragma unroll
    for (int j = 0; j < 12; j++) acc[j] = 0.f;
    float ws0 = 0.f, ws1 = 0.f, ws2 = 0.f;

    for (int e = beg; e < end; e++) {
        int s = g_csrsrc[e];
        float w0 = __expf(leaky(g_sns[s * 3 + 0] + snd0) - m0);
        float w1 = __expf(leaky(g_sns[s * 3 + 1] + snd1) - m1);
        float w2 = __expf(leaky(g_sns[s * 3 + 2] + snd2) - m2);
        ws0 += w0; ws1 += w1; ws2 += w2;
        const float* hr = g_h + (size_t)s * HD;
#pragma unroll
        for (int j = 0; j < 12; j++) {
            float wv = (j < 4) ? w0 : (j < 8) ? w1 : w2;
            acc[j] += wv * hr[j * 32 + lane];
        }
    }

    float r0 = ws0 > 0.f ? 1.f / ws0 : 0.f;
    float r1 = ws1 > 0.f ? 1.f / ws1 : 0.f;
    float r2 = ws2 > 0.f ? 1.f / ws2 : 0.f;
    __nv_bfloat16* ah = g_agghi + (size_t)v * HD;
    __nv_bfloat16* al = g_agglo + (size_t)v * HD;
#pragma unroll
    for (int j = 0; j < 12; j++) {
        float rv = (j < 4) ? r0 : (j < 8) ? r1 : r2;
        float val = acc[j] * rv;
        __nv_bfloat16 h, l; split_bf16(val, h, l);
        ah[j * 32 + lane] = h;
        al[j * 32 + lane] = l;
    }
}

// ---------------- global attention pooling ----------------
__global__ void pool_kernel(const float* __restrict__ feat, float* __restrict__ out, float scale) {
    int g = blockIdx.x;
    int d = threadIdx.x;
    int s = g_gstart[g], e = g_gend[g];
    __shared__ float red[128];

    float m = -1e30f;
    for (int i = s + d; i < e; i += 128) m = fmaxf(m, g_gate[i]);
    red[d] = m; __syncthreads();
    for (int o = 64; o; o >>= 1) { if (d < o) red[d] = fmaxf(red[d], red[d + o]); __syncthreads(); }
    m = red[0]; __syncthreads();

    float sum = 0.f;
    for (int i = s + d; i < e; i += 128) sum += __expf(g_gate[i] - m);
    red[d] = sum; __syncthreads();
    for (int o = 64; o; o >>= 1) { if (d < o) red[d] += red[d + o]; __syncthreads(); }
    sum = red[0]; __syncthreads();

    float accv = 0.f;
    for (int i = s; i < e; i++) {
        float wv = __expf(g_gate[i] - m);
        accv += wv * feat[(size_t)i * DD + d];
    }
    if (e > s && sum > 0.f) out[g * DD + d] += scale * accv / sum;
}

// ---------------- launch ----------------
extern "C" void kernel_launch(void* const* d_in, const int* in_sizes, int n_in,
                              void* d_out, int out_size)
{
    const float* feat    = (const float*)d_in[0];
    const int*   src     = (const int*)d_in[1];
    const int*   dst     = (const int*)d_in[2];
    const int*   gid     = (const int*)d_in[3];
    const float* fc_w    = (const float*)d_in[4];
    const float* a_ns    = (const float*)d_in[5];
    const float* a_nd    = (const float*)d_in[6];
    const float* trans_w = (const float*)d_in[7];
    const float* trans_b = (const float*)d_in[8];
    const float* p1_w    = (const float*)d_in[9];
    const float* p1_b    = (const float*)d_in[10];
    const float* p2_w    = (const float*)d_in[11];
    const float* p2_b    = (const float*)d_in[12];
    (void)p2_b;  // per-graph softmax over gate is shift-invariant
    float* out = (float*)d_out;

    float *p_h, *p_featA, *p_featB, *p_gate, *p_sns, *p_snd;
    cudaGetSymbolAddress((void**)&p_h, g_h);
    cudaGetSymbolAddress((void**)&p_featA, g_featA);
    cudaGetSymbolAddress((void**)&p_featB, g_featB);
    cudaGetSymbolAddress((void**)&p_gate, g_gate);
    cudaGetSymbolAddress((void**)&p_sns, g_sns);
    cudaGetSymbolAddress((void**)&p_snd, g_snd);

    __nv_bfloat16 *p_fhiA, *p_floA, *p_fhiB, *p_floB, *p_agghi, *p_agglo;
    __nv_bfloat16 *p_wfchi, *p_wfclo, *p_wtrhi, *p_wtrlo, *p_wcathi, *p_wcatlo;
    cudaGetSymbolAddress((void**)&p_fhiA, g_fhiA);
    cudaGetSymbolAddress((void**)&p_floA, g_floA);
    cudaGetSymbolAddress((void**)&p_fhiB, g_fhiB);
    cudaGetSymbolAddress((void**)&p_floB, g_floB);
    cudaGetSymbolAddress((void**)&p_agghi, g_agghi);
    cudaGetSymbolAddress((void**)&p_agglo, g_agglo);
    cudaGetSymbolAddress((void**)&p_wfchi, g_wfchi);
    cudaGetSymbolAddress((void**)&p_wfclo, g_wfclo);
    cudaGetSymbolAddress((void**)&p_wtrhi, g_wtrhi);
    cudaGetSymbolAddress((void**)&p_wtrlo, g_wtrlo);
    cudaGetSymbolAddress((void**)&p_wcathi, g_wcathi);
    cudaGetSymbolAddress((void**)&p_wcatlo, g_wcatlo);

    const int SMEM_GEMM = NSTAGE * STAGE_BYTES;   // 73728
    cudaFuncSetAttribute(gemm_bf16split, cudaFuncAttributeMaxDynamicSharedMemorySize, SMEM_GEMM);
    cudaFuncSetAttribute(scan_kernel, cudaFuncAttributeMaxDynamicSharedMemorySize, SCAN_SMEM);

    const int gx = (NN + 127) / 128;
    const int warpBlocks = (NN + 7) / 8;
    const int NCONV = LL*(HD*DD + DD*HD + TWO_D*DD);

    // launch 0: copy+split input, zero everything, init graph bounds
    copy_split_kernel<<<(NN * DD + 255) / 256, 256>>>(feat, out);
    // launch 1: weight converts + concat + hist + gbounds
    conv_all_kernel<<<(NCONV + 255) / 256, 256>>>(fc_w, trans_w, p1_w, dst, gid);

    // launch 2: layer-0 h-GEMM, all 384 columns (+ fused attn scores)
    gemm_bf16split<<<dim3(gx, HD / 64), 256, SMEM_GEMM>>>(NN, HD, DD, 0,
        p_fhiA, p_floA, p_wfchi, p_wfclo,
        (const float*)0, (const float*)0, p_h,
        (__nv_bfloat16*)0, (__nv_bfloat16*)0, 0,
        (float*)0, (const float*)0,
        p_sns, p_snd, a_ns, a_nd, 0, 0);

    // CSR build (by dst)
    scan_kernel<<<1, 1024, SCAN_SMEM>>>();
    scatter_kernel<<<(EE + 255) / 256, 256>>>(src, dst);

    for (int d = 0; d < LL; d++) {
        int pp = d & 1;
        float* fin  = pp ? p_featB : p_featA;
        float* fout = pp ? p_featA : p_featB;
        __nv_bfloat16* fouthi = pp ? p_fhiA : p_fhiB;
        __nv_bfloat16* foutlo = pp ? p_floA : p_floB;

        gat_edge_kernel<<<warpBlocks, 256>>>();

        // fout = relu?(agg @ trans_w[d]^T + b) + fin  (+ bf16 split out, + zero aux)
        gemm_bf16split<<<dim3(gx, DD / 64), 256, SMEM_GEMM>>>(NN, DD, HD, 0,
            p_agghi, p_agglo, p_wtrhi + (size_t)d * DD * HD, p_wtrlo + (size_t)d * DD * HD,
            trans_b + (size_t)d * DD, fin, fout, fouthi, foutlo, (d < LL - 1) ? 1 : 0,
            (float*)0, (const float*)0, (float*)0, (float*)0, (const float*)0, (const float*)0,
            0, 1);

        // combined: gate GEMM (cols 0..255) + next layer's h-GEMM (cols 256..639)
        int yB = (d < LL - 1) ? (NCAT / 64) : (TWO_D / 64);
        int dn = (d < LL - 1) ? (d + 1) : d;
        gemm_bf16split<<<dim3(gx, yB), 256, SMEM_GEMM>>>(NN, HD, DD, 0,
            fouthi, foutlo,
            p_wcathi + (size_t)d * NCAT * DD, p_wcatlo + (size_t)d * NCAT * DD,
            p1_b + (size_t)d * TWO_D, (const float*)0, (float*)0,
            (__nv_bfloat16*)0, (__nv_bfloat16*)0, 0,
            p_gate, p2_w + (size_t)d * TWO_D,
            p_sns, p_snd, a_ns + (size_t)dn * HD, a_nd + (size_t)dn * HD,
            1, 0);

        pool_kernel<<<GG, 128>>>(fout, out, 1.0f / LL);
    }
}

// round 15
// speedup vs baseline: 1.3599x; 1.1705x over previous
#include <cuda_runtime.h>
#include <cuda_bf16.h>
#include <stdint.h>
#include <math.h>

typedef unsigned int u32;

#define NN 20000
#define EE 320000
#define DD 128
#define HH 3
#define HD (HH*DD)      /* 384 */
#define LL 3
#define GG 64
#define TWO_D (2*DD)    /* 256 */
#define NCAT (TWO_D+HD) /* 640: [p1_w(d); fc_w(d+1)] */
#define NEG_SLOPE 0.2f

// ---------------- scratch (device globals; no allocation allowed) ----------------
__device__ float g_h[(size_t)NN*HD];
__device__ float g_featA[(size_t)NN*DD];
__device__ float g_featB[(size_t)NN*DD];
__device__ float g_gate[NN];
__device__ float g_sns[NN*HH];
__device__ float g_snd[NN*HH];
__device__ int   g_deg[NN];
__device__ int   g_rowptr[NN+1];
__device__ int   g_cursor[NN];
__device__ int   g_csrsrc[EE];
__device__ int   g_gstart[GG];
__device__ int   g_gend[GG];

// bf16 split buffers
__device__ __nv_bfloat16 g_fhiA[(size_t)NN*DD];
__device__ __nv_bfloat16 g_floA[(size_t)NN*DD];
__device__ __nv_bfloat16 g_fhiB[(size_t)NN*DD];
__device__ __nv_bfloat16 g_floB[(size_t)NN*DD];
__device__ __nv_bfloat16 g_agghi[(size_t)NN*HD];
__device__ __nv_bfloat16 g_agglo[(size_t)NN*HD];
__device__ __nv_bfloat16 g_wfchi[(size_t)LL*HD*DD];
__device__ __nv_bfloat16 g_wfclo[(size_t)LL*HD*DD];
__device__ __nv_bfloat16 g_wtrhi[(size_t)LL*DD*HD];
__device__ __nv_bfloat16 g_wtrlo[(size_t)LL*DD*HD];
__device__ __nv_bfloat16 g_wcathi[(size_t)LL*NCAT*DD];
__device__ __nv_bfloat16 g_wcatlo[(size_t)LL*NCAT*DD];

__device__ __forceinline__ void split_bf16(float v, __nv_bfloat16& hi, __nv_bfloat16& lo) {
    hi = __float2bfloat16_rn(v);
    lo = __float2bfloat16_rn(v - __bfloat162float(hi));
}

// ---------------- setup kernels ----------------
__global__ void copy_split_kernel(const float* __restrict__ srcp, float* __restrict__ out) {
    int i = blockIdx.x*blockDim.x + threadIdx.x;
    if (i < NN*DD) {
        float v = srcp[i];
        g_featA[i] = v;
        __nv_bfloat16 hi, lo; split_bf16(v, hi, lo);
        g_fhiA[i] = hi; g_floA[i] = lo;
    }
    if (i < NN*HH) { g_sns[i] = 0.f; g_snd[i] = 0.f; }
    if (i < NN)    { g_gate[i] = 0.f; g_deg[i] = 0; }
    if (i < GG*DD) out[i] = 0.f;
    if (i < GG)    { g_gstart[i] = NN; g_gend[i] = 0; }
}

__global__ void conv_all_kernel(const float* __restrict__ fc, const float* __restrict__ tr,
                                const float* __restrict__ p1,
                                const int* __restrict__ dst, const int* __restrict__ gid) {
    const int NFC = LL*HD*DD;
    const int NTR = LL*DD*HD;
    const int NP1 = LL*TWO_D*DD;
    int i = blockIdx.x*blockDim.x + threadIdx.x;
    if (i < NFC) {
        __nv_bfloat16 h, l; split_bf16(fc[i], h, l);
        g_wfchi[i] = h; g_wfclo[i] = l;
        int d = i / (HD*DD);
        if (d >= 1) {
            int r = i - d * (HD*DD);
            size_t ci = (size_t)(d-1) * NCAT * DD + (size_t)TWO_D * DD + r;
            g_wcathi[ci] = h; g_wcatlo[ci] = l;
        }
    } else if (i < NFC + NTR) {
        int j = i - NFC;
        __nv_bfloat16 h, l; split_bf16(tr[j], h, l);
        g_wtrhi[j] = h; g_wtrlo[j] = l;
    } else if (i < NFC + NTR + NP1) {
        int j = i - NFC - NTR;
        __nv_bfloat16 h, l; split_bf16(p1[j], h, l);
        int d = j / (TWO_D*DD);
        int r = j - d * (TWO_D*DD);
        size_t ci = (size_t)d * NCAT * DD + r;
        g_wcathi[ci] = h; g_wcatlo[ci] = l;
    }
    if (i < EE) atomicAdd(&g_deg[dst[i]], 1);
    if (i < NN) {
        int g = gid[i];
        atomicMin(&g_gstart[g], i);
        atomicMax(&g_gend[g], i + 1);
    }
}

// ---- single-block prefix scan, smem-staged, coalesced IO ----
#define SCAN_CH 20
#define SCAN_SMEM ((NN + 1024) * (int)sizeof(int))   /* 84096 B */
__global__ void scan_kernel() {
    extern __shared__ int sm[];
    int* vals = sm;
    int* part = sm + NN;
    const int t = threadIdx.x;

    for (int j = t; j < NN; j += 1024) vals[j] = g_deg[j];
    __syncthreads();

    const int base = t * SCAN_CH;
    int s = 0;
#pragma unroll
    for (int i = 0; i < SCAN_CH; i++) {
        int idx = base + i;
        if (idx < NN) {
            int v = vals[idx];
            vals[idx] = s;
            s += v;
        }
    }
    part[t] = s;
    __syncthreads();

    for (int off = 1; off < 1024; off <<= 1) {
        int v = (t >= off) ? part[t - off] : 0;
        __syncthreads();
        part[t] += v;
        __syncthreads();
    }

    for (int j = t; j < NN; j += 1024) {
        int c = j / SCAN_CH;
        int off = (c > 0) ? part[c - 1] : 0;
        int r = off + vals[j];
        g_rowptr[j] = r;
        g_cursor[j] = r;
    }
    if (t == 0) g_rowptr[NN] = part[1023];
}

__global__ void scatter_kernel(const int* __restrict__ src, const int* __restrict__ dst) {
    int e = blockIdx.x*blockDim.x + threadIdx.x;
    if (e < EE) {
        int p = atomicAdd(&g_cursor[dst[e]], 1);
        g_csrsrc[p] = src[e];
    }
}

// ---------------- tensor-core GEMM (3-stage cp.async, swizzled smem, 1 sync/chunk) ----
__device__ __forceinline__ void ldm_x4(u32 addr, u32& r0, u32& r1, u32& r2, u32& r3) {
    asm volatile("ldmatrix.sync.aligned.m8n8.x4.shared.b16 {%0,%1,%2,%3}, [%4];"
        : "=r"(r0), "=r"(r1), "=r"(r2), "=r"(r3) : "r"(addr));
}

__device__ __forceinline__ void mma16816(float* c, const u32* a, const u32* b) {
    asm volatile(
        "mma.sync.aligned.m16n8k16.row.col.f32.bf16.bf16.f32 "
        "{%0,%1,%2,%3}, {%4,%5,%6,%7}, {%8,%9}, {%0,%1,%2,%3};"
        : "+f"(c[0]), "+f"(c[1]), "+f"(c[2]), "+f"(c[3])
        : "r"(a[0]), "r"(a[1]), "r"(a[2]), "r"(a[3]), "r"(b[0]), "r"(b[1]));
}

#define CP16(dst, src, sz) asm volatile( \
    "cp.async.cg.shared.global [%0], [%1], 16, %2;" :: "r"(dst), "l"(src), "r"(sz))
#define CP_COMMIT() asm volatile("cp.async.commit_group;")
#define CP_WAIT1()  asm volatile("cp.async.wait_group 1;")
#define CP_WAIT0()  asm volatile("cp.async.wait_group 0;")

#define A_BYTES (128*64)
#define B_BYTES (64*64)
#define STAGE_BYTES (2*A_BYTES + 2*B_BYTES)   /* 24576 */
#define NSTAGE 3
#define SWZ(row, c) (((u32)(row) << 6) + (u32)(((c) ^ (((row) >> 1) & 3)) << 4))

#define GISSUE(kc, st) { \
    int kb = ((kc) << 5) + cq * 8; \
    u32 sbase = smem_u + (u32)((st) * STAGE_BYTES); \
    CP16(sbase + aoff0,                       Ahi + (size_t)arow0c * K + kb, szA0); \
    CP16(sbase + aoff0 + 4096u,               Ahi + (size_t)arow1c * K + kb, szA1); \
    CP16(sbase + (u32)A_BYTES + aoff0,        Alo + (size_t)arow0c * K + kb, szA0); \
    CP16(sbase + (u32)A_BYTES + aoff0 + 4096u, Alo + (size_t)arow1c * K + kb, szA1); \
    CP16(sbase + (u32)(2*A_BYTES) + boff,     Bhi + (size_t)(n0 + br0) * K + kb, 16); \
    CP16(sbase + (u32)(2*A_BYTES + B_BYTES) + boff, Blo + (size_t)(n0 + br0) * K + kb, 16); \
}

__global__ void __launch_bounds__(256, 3) gemm_bf16split(
    int M, int Nd, int K, int col_base,
    const __nv_bfloat16* __restrict__ Ahi, const __nv_bfloat16* __restrict__ Alo,
    const __nv_bfloat16* __restrict__ Bhi, const __nv_bfloat16* __restrict__ Blo,
    const float* __restrict__ bias, const float* __restrict__ resid,
    float* __restrict__ C, __nv_bfloat16* __restrict__ Chi, __nv_bfloat16* __restrict__ Clo,
    int do_relu,
    float* __restrict__ gatep, const float* __restrict__ p2w,
    float* __restrict__ snsp, float* __restrict__ sndp,
    const float* __restrict__ ansp, const float* __restrict__ andp,
    int combined, int zero_aux)
{
    extern __shared__ __nv_bfloat16 smem[];

    const int tid  = threadIdx.x;
    const int lane = tid & 31;
    const int w    = tid >> 5;
    const int wm   = w & 3;
    const int wn   = w >> 2;
    const int m0   = blockIdx.x * 128;
    const int n0   = blockIdx.y * 64;
    const int nk   = K >> 5;

    float acc[2][4][4];
#pragma unroll
    for (int a = 0; a < 2; a++)
#pragma unroll
        for (int b = 0; b < 4; b++)
#pragma unroll
            for (int c = 0; c < 4; c++) acc[a][b][c] = 0.f;

    const u32 smem_u = (u32)__cvta_generic_to_shared(smem);

    const int a_row_in = (lane & 7) + ((lane >> 3) & 1) * 8;
    const int a_chalf  = lane >> 4;
    const int b_sub    = lane >> 3;
    const int b_row_in = (lane & 7) + (b_sub >> 1) * 8;
    const int b_chalf  = b_sub & 1;

    const int ar0 = tid >> 2;
    const int cq  = tid & 3;
    const int br0 = ar0;
    const int arow0 = m0 + ar0;
    const int arow1 = m0 + ar0 + 64;
    const int arow0c = (arow0 < M) ? arow0 : (M - 1);
    const int arow1c = (arow1 < M) ? arow1 : (M - 1);
    const u32 szA0 = (arow0 < M) ? 16u : 0u;
    const u32 szA1 = (arow1 < M) ? 16u : 0u;
    const u32 aoff0 = SWZ(ar0, cq);
    const u32 boff  = SWZ(br0, cq);

    GISSUE(0, 0);
    CP_COMMIT();
    if (nk > 1) { GISSUE(1, 1); CP_COMMIT(); }

    int cur = 0;
    for (int kc = 0; kc < nk; kc++) {
        if (kc + 1 < nk) { CP_WAIT1(); } else { CP_WAIT0(); }
        __syncthreads();

        if (kc + 2 < nk) {
            int st = kc + 2 - ((kc + 2) / NSTAGE) * NSTAGE;
            GISSUE(kc + 2, st);
            CP_COMMIT();
        }

        const u32 stbase = smem_u + (u32)(cur * STAGE_BYTES);
#pragma unroll
        for (int ks = 0; ks < 2; ks++) {
            u32 Af[2][2][4];
            u32 Bf[2][4][2];
#pragma unroll
            for (int hl = 0; hl < 2; hl++) {
                const u32 abase = stbase + (u32)(hl * A_BYTES);
#pragma unroll
                for (int mt = 0; mt < 2; mt++) {
                    int row = wm * 32 + mt * 16 + a_row_in;
                    u32 addr = abase + SWZ(row, ks * 2 + a_chalf);
                    ldm_x4(addr, Af[hl][mt][0], Af[hl][mt][1], Af[hl][mt][2], Af[hl][mt][3]);
                }
                const u32 bbase = stbase + (u32)(2 * A_BYTES + hl * B_BYTES);
#pragma unroll
                for (int pr = 0; pr < 2; pr++) {
                    int row = wn * 32 + pr * 16 + b_row_in;
                    u32 addr2 = bbase + SWZ(row, ks * 2 + b_chalf);
                    u32 q0, q1, q2, q3;
                    ldm_x4(addr2, q0, q1, q2, q3);
                    Bf[hl][pr * 2 + 0][0] = q0; Bf[hl][pr * 2 + 0][1] = q1;
                    Bf[hl][pr * 2 + 1][0] = q2; Bf[hl][pr * 2 + 1][1] = q3;
                }
            }
#pragma unroll
            for (int term = 0; term < 3; term++) {
                const int ahl = (term == 2) ? 1 : 0;
                const int bhl = (term == 1) ? 1 : 0;
#pragma unroll
                for (int mt = 0; mt < 2; mt++)
#pragma unroll
                    for (int nt = 0; nt < 4; nt++)
                        mma16816(acc[mt][nt], Af[ahl][mt], Bf[bhl][nt]);
            }
        }
        cur++; if (cur == NSTAGE) cur = 0;
    }

    // epilogue
    const int gr = lane >> 2;
    const int gc = (lane & 3) * 2;
    const int wspan = col_base + n0 + wn * 32;
    const bool isGate = wspan < TWO_D;
    const int head = combined ? ((wspan - TWO_D) >> 7) : (wspan >> 7);
#pragma unroll
    for (int mt = 0; mt < 2; mt++) {
#pragma unroll
        for (int half = 0; half < 2; half++) {
            int m = m0 + wm * 32 + mt * 16 + gr + half * 8;
            if (m >= M) continue;
            float gpart = 0.f, ps = 0.f, pt = 0.f;
#pragma unroll
            for (int nt = 0; nt < 4; nt++) {
                int gn = col_base + n0 + wn * 32 + nt * 8 + gc;
                float v0 = acc[mt][nt][half * 2 + 0];
                float v1 = acc[mt][nt][half * 2 + 1];
                if (combined) {
                    if (isGate) {
                        v0 += bias[gn]; v1 += bias[gn + 1];
                        v0 = fmaxf(v0, 0.f); v1 = fmaxf(v1, 0.f);
                        gpart += v0 * __ldg(p2w + gn) + v1 * __ldg(p2w + gn + 1);
                    } else {
                        int hc = gn - TWO_D;
                        ps += v0 * __ldg(ansp + hc) + v1 * __ldg(ansp + hc + 1);
                        pt += v0 * __ldg(andp + hc) + v1 * __ldg(andp + hc + 1);
                        float2 vv; vv.x = v0; vv.y = v1;
                        *(float2*)(g_h + (size_t)m * HD + hc) = vv;
                    }
                    continue;
                }
                if (bias) { v0 += bias[gn]; v1 += bias[gn + 1]; }
                if (do_relu) { v0 = fmaxf(v0, 0.f); v1 = fmaxf(v1, 0.f); }
                if (resid) {
                    v0 += resid[(size_t)m * Nd + gn];
                    v1 += resid[(size_t)m * Nd + gn + 1];
                }
                if (gatep) {
                    gpart += v0 * __ldg(p2w + gn) + v1 * __ldg(p2w + gn + 1);
                }
                if (snsp) {
                    ps += v0 * __ldg(ansp + gn) + v1 * __ldg(ansp + gn + 1);
                    pt += v0 * __ldg(andp + gn) + v1 * __ldg(andp + gn + 1);
                }
                if (C) {
                    float2 vv; vv.x = v0; vv.y = v1;
                    *(float2*)(C + (size_t)m * Nd + gn) = vv;
                }
                if (Chi) {
                    __nv_bfloat16 h0, l0, h1, l1;
                    split_bf16(v0, h0, l0);
                    split_bf16(v1, h1, l1);
                    __nv_bfloat162 hh; hh.x = h0; hh.y = h1;
                    __nv_bfloat162 ll; ll.x = l0; ll.y = l1;
                    *(__nv_bfloat162*)(Chi + (size_t)m * Nd + gn) = hh;
                    *(__nv_bfloat162*)(Clo + (size_t)m * Nd + gn) = ll;
                }
            }
            if (combined) {
                if (isGate) atomicAdd(gatep + m, gpart);
                else {
                    atomicAdd(snsp + m * 3 + head, ps);
                    atomicAdd(sndp + m * 3 + head, pt);
                }
            } else {
                if (gatep) atomicAdd(gatep + m, gpart);
                if (snsp) {
                    atomicAdd(snsp + m * 3 + head, ps);
                    atomicAdd(sndp + m * 3 + head, pt);
                }
            }
            if (zero_aux) {
                g_sns[m * 3 + 0] = 0.f; g_sns[m * 3 + 1] = 0.f; g_sns[m * 3 + 2] = 0.f;
                g_snd[m * 3 + 0] = 0.f; g_snd[m * 3 + 1] = 0.f; g_snd[m * 3 + 2] = 0.f;
                g_gate[m] = 0.f;
            }
        }
    }
}

// ---------------- edge softmax + aggregation: one warp per dst node ----------------
__device__ __forceinline__ float leaky(float x) { return x > 0.f ? x : NEG_SLOPE * x; }

__global__ void gat_edge_kernel() {
    int v = (blockIdx.x * blockDim.x + threadIdx.x) >> 5;
    int lane = threadIdx.x & 31;
    if (v >= NN) return;
    int beg = g_rowptr[v], end = g_rowptr[v + 1];
    float snd0 = g_snd[v * 3 + 0], snd1 = g_snd[v * 3 + 1], snd2 = g_snd[v * 3 + 2];

    float m0 = -1e30f, m1 = -1e30f, m2 = -1e30f;
    for (int e = beg + lane; e < end; e += 32) {
        int s = g_csrsrc[e];
        m0 = fmaxf(m0, leaky(g_sns[s * 3 + 0] + snd0));
        m1 = fmaxf(m1, leaky(g_sns[s * 3 + 1] + snd1));
        m2 = fmaxf(m2, leaky(g_sns[s * 3 + 2] + snd2));
    }
#pragma unroll
    for (int o = 16; o; o >>= 1) {
        m0 = fmaxf(m0, __shfl_xor_sync(0xffffffffu, m0, o));
        m1 = fmaxf(m1, __shfl_xor_sync(0xffffffffu, m1, o));
        m2 = fmaxf(m2, __shfl_xor_sync(0xffffffffu, m2, o));
    }

    float acc[12];
#pragma unroll
    for (int j = 0; j < 12; j++) acc[j] = 0.f;
    float ws0 = 0.f, ws1 = 0.f, ws2 = 0.f;

    for (int e = beg; e < end; e++) {
        int s = g_csrsrc[e];
        float w0 = __expf(leaky(g_sns[s * 3 + 0] + snd0) - m0);
        float w1 = __expf(leaky(g_sns[s * 3 + 1] + snd1) - m1);
        float w2 = __expf(leaky(g_sns[s * 3 + 2] + snd2) - m2);
        ws0 += w0; ws1 += w1; ws2 += w2;
        const float* hr = g_h + (size_t)s * HD;
#pragma unroll
        for (int j = 0; j < 12; j++) {
            float wv = (j < 4) ? w0 : (j < 8) ? w1 : w2;
            acc[j] += wv * hr[j * 32 + lane];
        }
    }

    float r0 = ws0 > 0.f ? 1.f / ws0 : 0.f;
    float r1 = ws1 > 0.f ? 1.f / ws1 : 0.f;
    float r2 = ws2 > 0.f ? 1.f / ws2 : 0.f;
    __nv_bfloat16* ah = g_agghi + (size_t)v * HD;
    __nv_bfloat16* al = g_agglo + (size_t)v * HD;
#pragma unroll
    for (int j = 0; j < 12; j++) {
        float rv = (j < 4) ? r0 : (j < 8) ? r1 : r2;
        float val = acc[j] * rv;
        __nv_bfloat16 h, l; split_bf16(val, h, l);
        ah[j * 32 + lane] = h;
        al[j * 32 + lane] = l;
    }
}

// ---------------- global attention pooling ----------------
__global__ void pool_kernel(const float* __restrict__ feat, float* __restrict__ out, float scale) {
    int g = blockIdx.x;
    int d = threadIdx.x;
    int s = g_gstart[g], e = g_gend[g];
    __shared__ float red[128];

    float m = -1e30f;
    for (int i = s + d; i < e; i += 128) m = fmaxf(m, g_gate[i]);
    red[d] = m; __syncthreads();
    for (int o = 64; o; o >>= 1) { if (d < o) red[d] = fmaxf(red[d], red[d + o]); __syncthreads(); }
    m = red[0]; __syncthreads();

    float sum = 0.f;
    for (int i = s + d; i < e; i += 128) sum += __expf(g_gate[i] - m);
    red[d] = sum; __syncthreads();
    for (int o = 64; o; o >>= 1) { if (d < o) red[d] += red[d + o]; __syncthreads(); }
    sum = red[0]; __syncthreads();

    float accv = 0.f;
    for (int i = s; i < e; i++) {
        float wv = __expf(g_gate[i] - m);
        accv += wv * feat[(size_t)i * DD + d];
    }
    if (e > s && sum > 0.f) out[g * DD + d] += scale * accv / sum;
}

// ---------------- launch ----------------
extern "C" void kernel_launch(void* const* d_in, const int* in_sizes, int n_in,
                              void* d_out, int out_size)
{
    const float* feat    = (const float*)d_in[0];
    const int*   src     = (const int*)d_in[1];
    const int*   dst     = (const int*)d_in[2];
    const int*   gid     = (const int*)d_in[3];
    const float* fc_w    = (const float*)d_in[4];
    const float* a_ns    = (const float*)d_in[5];
    const float* a_nd    = (const float*)d_in[6];
    const float* trans_w = (const float*)d_in[7];
    const float* trans_b = (const float*)d_in[8];
    const float* p1_w    = (const float*)d_in[9];
    const float* p1_b    = (const float*)d_in[10];
    const float* p2_w    = (const float*)d_in[11];
    const float* p2_b    = (const float*)d_in[12];
    (void)p2_b;  // per-graph softmax over gate is shift-invariant
    float* out = (float*)d_out;

    // side stream + events (created once, on the uncaptured correctness call)
    static cudaStream_t sB = 0;
    static cudaEvent_t evFork = 0, evCSR = 0, evComb[LL], evPool[LL];
    if (!sB) {
        cudaStreamCreateWithFlags(&sB, cudaStreamNonBlocking);
        cudaEventCreateWithFlags(&evFork, cudaEventDisableTiming);
        cudaEventCreateWithFlags(&evCSR, cudaEventDisableTiming);
        for (int d = 0; d < LL; d++) {
            cudaEventCreateWithFlags(&evComb[d], cudaEventDisableTiming);
            cudaEventCreateWithFlags(&evPool[d], cudaEventDisableTiming);
        }
    }

    float *p_h, *p_featA, *p_featB, *p_gate, *p_sns, *p_snd;
    cudaGetSymbolAddress((void**)&p_h, g_h);
    cudaGetSymbolAddress((void**)&p_featA, g_featA);
    cudaGetSymbolAddress((void**)&p_featB, g_featB);
    cudaGetSymbolAddress((void**)&p_gate, g_gate);
    cudaGetSymbolAddress((void**)&p_sns, g_sns);
    cudaGetSymbolAddress((void**)&p_snd, g_snd);

    __nv_bfloat16 *p_fhiA, *p_floA, *p_fhiB, *p_floB, *p_agghi, *p_agglo;
    __nv_bfloat16 *p_wfchi, *p_wfclo, *p_wtrhi, *p_wtrlo, *p_wcathi, *p_wcatlo;
    cudaGetSymbolAddress((void**)&p_fhiA, g_fhiA);
    cudaGetSymbolAddress((void**)&p_floA, g_floA);
    cudaGetSymbolAddress((void**)&p_fhiB, g_fhiB);
    cudaGetSymbolAddress((void**)&p_floB, g_floB);
    cudaGetSymbolAddress((void**)&p_agghi, g_agghi);
    cudaGetSymbolAddress((void**)&p_agglo, g_agglo);
    cudaGetSymbolAddress((void**)&p_wfchi, g_wfchi);
    cudaGetSymbolAddress((void**)&p_wfclo, g_wfclo);
    cudaGetSymbolAddress((void**)&p_wtrhi, g_wtrhi);
    cudaGetSymbolAddress((void**)&p_wtrlo, g_wtrlo);
    cudaGetSymbolAddress((void**)&p_wcathi, g_wcathi);
    cudaGetSymbolAddress((void**)&p_wcatlo, g_wcatlo);

    const int SMEM_GEMM = NSTAGE * STAGE_BYTES;   // 73728
    cudaFuncSetAttribute(gemm_bf16split, cudaFuncAttributeMaxDynamicSharedMemorySize, SMEM_GEMM);
    cudaFuncSetAttribute(scan_kernel, cudaFuncAttributeMaxDynamicSharedMemorySize, SCAN_SMEM);

    const int gx = (NN + 127) / 128;
    const int warpBlocks = (NN + 7) / 8;
    const int NCONV = LL*(HD*DD + DD*HD + TWO_D*DD);

    // main: setup
    copy_split_kernel<<<(NN * DD + 255) / 256, 256>>>(feat, out);
    conv_all_kernel<<<(NCONV + 255) / 256, 256>>>(fc_w, trans_w, p1_w, dst, gid);
    cudaEventRecord(evFork, 0);

    // side stream: CSR build (scan + scatter) concurrent with h-GEMM below
    cudaStreamWaitEvent(sB, evFork, 0);
    scan_kernel<<<1, 1024, SCAN_SMEM, sB>>>();
    scatter_kernel<<<(EE + 255) / 256, 256, 0, sB>>>(src, dst);
    cudaEventRecord(evCSR, sB);

    // main: layer-0 h-GEMM (+ fused attn scores)
    gemm_bf16split<<<dim3(gx, HD / 64), 256, SMEM_GEMM>>>(NN, HD, DD, 0,
        p_fhiA, p_floA, p_wfchi, p_wfclo,
        (const float*)0, (const float*)0, p_h,
        (__nv_bfloat16*)0, (__nv_bfloat16*)0, 0,
        (float*)0, (const float*)0,
        p_sns, p_snd, a_ns, a_nd, 0, 0);

    cudaStreamWaitEvent(0, evCSR, 0);   // join CSR before first edge kernel

    for (int d = 0; d < LL; d++) {
        int pp = d & 1;
        float* fin  = pp ? p_featB : p_featA;
        float* fout = pp ? p_featA : p_featB;
        __nv_bfloat16* fouthi = pp ? p_fhiA : p_fhiB;
        __nv_bfloat16* foutlo = pp ? p_floA : p_floB;

        gat_edge_kernel<<<warpBlocks, 256>>>();

        // gemm2 zeroes g_gate -> must wait for pool(d-1) reading it
        if (d > 0) cudaStreamWaitEvent(0, evPool[d-1], 0);

        // fout = relu?(agg @ trans_w[d]^T + b) + fin  (+ bf16 split out, + zero aux)
        gemm_bf16split<<<dim3(gx, DD / 64), 256, SMEM_GEMM>>>(NN, DD, HD, 0,
            p_agghi, p_agglo, p_wtrhi + (size_t)d * DD * HD, p_wtrlo + (size_t)d * DD * HD,
            trans_b + (size_t)d * DD, fin, fout, fouthi, foutlo, (d < LL - 1) ? 1 : 0,
            (float*)0, (const float*)0, (float*)0, (float*)0, (const float*)0, (const float*)0,
            0, 1);

        // combined: gate GEMM (cols 0..255) + next layer's h-GEMM (cols 256..639)
        int yB = (d < LL - 1) ? (NCAT / 64) : (TWO_D / 64);
        int dn = (d < LL - 1) ? (d + 1) : d;
        gemm_bf16split<<<dim3(gx, yB), 256, SMEM_GEMM>>>(NN, HD, DD, 0,
            fouthi, foutlo,
            p_wcathi + (size_t)d * NCAT * DD, p_wcatlo + (size_t)d * NCAT * DD,
            p1_b + (size_t)d * TWO_D, (const float*)0, (float*)0,
            (__nv_bfloat16*)0, (__nv_bfloat16*)0, 0,
            p_gate, p2_w + (size_t)d * TWO_D,
            p_sns, p_snd, a_ns + (size_t)dn * HD, a_nd + (size_t)dn * HD,
            1, 0);
        cudaEventRecord(evComb[d], 0);

        // pool(d) on side stream, overlapping next layer's edge kernel
        cudaStreamWaitEvent(sB, evComb[d], 0);
        pool_kernel<<<GG, 128, 0, sB>>>(fout, out, 1.0f / LL);
        cudaEventRecord(evPool[d], sB);
    }

    // join all side-stream work back to main before return
    cudaStreamWaitEvent(0, evPool[LL-1], 0);
}